// round 1
// baseline (speedup 1.0000x reference)
#include <cuda_runtime.h>
#include <cuda_bf16.h>
#include <cstdint>

// Problem constants
#define HID 512
#define POOL 4096
#define N_OBJ 1280
#define N_REL 16384
#define NUM_OBJ_CLS 151
#define NUM_REL_CLS 51

// -------- scratch (device globals; no allocation allowed) --------
__device__ float g_edge_rep[N_OBJ * 2 * HID];     // 1280 x 1024
__device__ float g_head_cat[N_OBJ * POOL];        // 1280 x 4096 (includes b_post_cat)
__device__ float g_tail_cat[N_OBJ * POOL];        // 1280 x 4096

// =====================================================================
// Generic fp32 SGEMM with optional bias: C = A @ B (+ bias)
// BM=BN=128, BK=8, 256 threads, 8x8 per-thread microtile.
// Requires M%128==0, N%128==0, K%8==0 (true for all our shapes).
// =====================================================================
#define BM 128
#define BN 128
#define BKK 8

__global__ __launch_bounds__(256) void sgemm_bias(
    const float* __restrict__ A, int lda,
    const float* __restrict__ B, int ldb,
    float* __restrict__ C, int ldc,
    const float* __restrict__ bias,
    int K)
{
    __shared__ float As[BKK][BM];
    __shared__ float Bs[BKK][BN];

    const int tid = threadIdx.x;
    const int rowBase = blockIdx.y * BM;
    const int colBase = blockIdx.x * BN;

    // A tile load mapping: 128 rows x 8 cols, one float4 per thread
    const int aRow = tid >> 1;
    const int aCol = (tid & 1) * 4;
    // B tile load mapping: 8 rows x 128 cols, one float4 per thread
    const int bRow = tid >> 5;
    const int bCol = (tid & 31) * 4;

    const float* Aptr = A + (size_t)(rowBase + aRow) * lda + aCol;
    const float* Bptr = B + (size_t)bRow * ldb + colBase + bCol;

    const int tr = tid >> 4;   // 0..15
    const int tc = tid & 15;   // 0..15

    float acc[8][8];
    #pragma unroll
    for (int m = 0; m < 8; m++)
        #pragma unroll
        for (int n = 0; n < 8; n++) acc[m][n] = 0.0f;

    for (int k0 = 0; k0 < K; k0 += BKK) {
        float4 a4 = *(const float4*)(Aptr + k0);
        float4 b4 = *(const float4*)(Bptr + (size_t)k0 * ldb);
        __syncthreads();
        As[aCol + 0][aRow] = a4.x;
        As[aCol + 1][aRow] = a4.y;
        As[aCol + 2][aRow] = a4.z;
        As[aCol + 3][aRow] = a4.w;
        *(float4*)&Bs[bRow][bCol] = b4;
        __syncthreads();

        #pragma unroll
        for (int kk = 0; kk < BKK; kk++) {
            float ra[8], rb[8];
            float4 ra0 = *(const float4*)&As[kk][tr * 8];
            float4 ra1 = *(const float4*)&As[kk][tr * 8 + 4];
            float4 rb0 = *(const float4*)&Bs[kk][tc * 8];
            float4 rb1 = *(const float4*)&Bs[kk][tc * 8 + 4];
            ra[0]=ra0.x; ra[1]=ra0.y; ra[2]=ra0.z; ra[3]=ra0.w;
            ra[4]=ra1.x; ra[5]=ra1.y; ra[6]=ra1.z; ra[7]=ra1.w;
            rb[0]=rb0.x; rb[1]=rb0.y; rb[2]=rb0.z; rb[3]=rb0.w;
            rb[4]=rb1.x; rb[5]=rb1.y; rb[6]=rb1.z; rb[7]=rb1.w;
            #pragma unroll
            for (int m = 0; m < 8; m++)
                #pragma unroll
                for (int n = 0; n < 8; n++)
                    acc[m][n] = fmaf(ra[m], rb[n], acc[m][n]);
        }
    }

    #pragma unroll
    for (int m = 0; m < 8; m++) {
        const int row = rowBase + tr * 8 + m;
        #pragma unroll
        for (int n = 0; n < 8; n += 4) {
            const int col = colBase + tc * 8 + n;
            float4 v;
            v.x = acc[m][n + 0];
            v.y = acc[m][n + 1];
            v.z = acc[m][n + 2];
            v.w = acc[m][n + 3];
            if (bias) {
                v.x += bias[col + 0];
                v.y += bias[col + 1];
                v.z += bias[col + 2];
                v.w += bias[col + 3];
            }
            *(float4*)&C[(size_t)row * ldc + col] = v;
        }
    }
}

// =====================================================================
// Fused epilogue: per relation r with pair (i,j):
//   m[k] = (head_cat[i,k] + tail_cat[j,k]) * U[r,k]     (b_post_cat folded into head_cat)
//   out[r,c] = sum_k m[k]*W_rel[k,c] + b_rel[c] + freq[obj[i]*151+obj[j], c]
// One warp handles 2 rows; k split across lanes; W_rel chunk in smem.
// =====================================================================
#define KC 128   // k-chunk

__global__ __launch_bounds__(256) void fused_rel(
    const float* __restrict__ U,
    const float* __restrict__ HC,
    const float* __restrict__ TC,
    const float* __restrict__ Wr,     // [4096, 51] row-major
    const float* __restrict__ br,     // [51]
    const float* __restrict__ freq,   // [151*151, 51]
    const int* __restrict__ pair_idx, // [16384, 2]
    const int* __restrict__ obj_preds,// [1280]
    float* __restrict__ out)          // [16384, 51]
{
    __shared__ float Ws[KC * NUM_REL_CLS];   // 128*51*4 = 26112 B

    const int warp = threadIdx.x >> 5;
    const int lane = threadIdx.x & 31;
    const int r0 = blockIdx.x * 16 + warp * 2;
    const int r1 = r0 + 1;

    const int i0 = pair_idx[2 * r0], j0 = pair_idx[2 * r0 + 1];
    const int i1 = pair_idx[2 * r1], j1 = pair_idx[2 * r1 + 1];

    const float* hc0 = HC + (size_t)i0 * POOL;
    const float* tc0 = TC + (size_t)j0 * POOL;
    const float* u0  = U  + (size_t)r0 * POOL;
    const float* hc1 = HC + (size_t)i1 * POOL;
    const float* tc1 = TC + (size_t)j1 * POOL;
    const float* u1  = U  + (size_t)r1 * POOL;

    float acc0[NUM_REL_CLS], acc1[NUM_REL_CLS];
    #pragma unroll
    for (int c = 0; c < NUM_REL_CLS; c++) { acc0[c] = 0.0f; acc1[c] = 0.0f; }

    for (int k0 = 0; k0 < POOL; k0 += KC) {
        __syncthreads();
        for (int idx = threadIdx.x; idx < KC * NUM_REL_CLS; idx += 256)
            Ws[idx] = Wr[(size_t)k0 * NUM_REL_CLS + idx];
        __syncthreads();

        #pragma unroll
        for (int kk = 0; kk < KC / 32; kk++) {
            const int kl = kk * 32 + lane;
            const int k = k0 + kl;
            const float m0 = (hc0[k] + tc0[k]) * u0[k];
            const float m1 = (hc1[k] + tc1[k]) * u1[k];
            const float* w = &Ws[kl * NUM_REL_CLS];
            #pragma unroll
            for (int c = 0; c < NUM_REL_CLS; c++) {
                const float wv = w[c];
                acc0[c] = fmaf(m0, wv, acc0[c]);
                acc1[c] = fmaf(m1, wv, acc1[c]);
            }
        }
    }

    const int b0 = obj_preds[i0] * NUM_OBJ_CLS + obj_preds[j0];
    const int b1 = obj_preds[i1] * NUM_OBJ_CLS + obj_preds[j1];

    // Cross-lane reduce per column (c is compile-time constant => accs stay
    // in registers). One lane per column writes the final value.
    #pragma unroll
    for (int c = 0; c < NUM_REL_CLS; c++) {
        float v0 = acc0[c];
        float v1 = acc1[c];
        #pragma unroll
        for (int off = 16; off; off >>= 1) {
            v0 += __shfl_xor_sync(0xffffffffu, v0, off);
            v1 += __shfl_xor_sync(0xffffffffu, v1, off);
        }
        if (lane == (c & 31)) {
            const float bc = br[c];
            out[(size_t)r0 * NUM_REL_CLS + c] = v0 + bc + freq[(size_t)b0 * NUM_REL_CLS + c];
            out[(size_t)r1 * NUM_REL_CLS + c] = v1 + bc + freq[(size_t)b1 * NUM_REL_CLS + c];
        }
    }
}

// =====================================================================
// Launch
// =====================================================================
extern "C" void kernel_launch(void* const* d_in, const int* in_sizes, int n_in,
                              void* d_out, int out_size)
{
    const float* edge_ctx   = (const float*)d_in[0];  // [1280, 512]
    const float* U          = (const float*)d_in[1];  // [16384, 4096]
    const float* W_post_emb = (const float*)d_in[2];  // [512, 1024]
    const float* b_post_emb = (const float*)d_in[3];  // [1024]
    const float* W_post_cat = (const float*)d_in[4];  // [1024, 4096]
    const float* b_post_cat = (const float*)d_in[5];  // [4096]
    const float* W_rel      = (const float*)d_in[6];  // [4096, 51]
    const float* b_rel      = (const float*)d_in[7];  // [51]
    const float* freq       = (const float*)d_in[8];  // [151*151, 51]
    const int*   pair_idx   = (const int*)d_in[9];    // [16384, 2]
    const int*   obj_preds  = (const int*)d_in[10];   // [1280]
    float* out = (float*)d_out;

    float *ep, *hc, *tc;
    cudaGetSymbolAddress((void**)&ep, g_edge_rep);
    cudaGetSymbolAddress((void**)&hc, g_head_cat);
    cudaGetSymbolAddress((void**)&tc, g_tail_cat);

    // K1: edge_rep = edge_ctx @ W_post_emb + b_post_emb    [1280 x 1024]
    sgemm_bias<<<dim3((2 * HID) / BN, N_OBJ / BM), 256>>>(
        edge_ctx, HID, W_post_emb, 2 * HID, ep, 2 * HID, b_post_emb, HID);

    // K2a: head_cat = edge_rep[:, :512] @ W_post_cat[:512] + b_post_cat
    sgemm_bias<<<dim3(POOL / BN, N_OBJ / BM), 256>>>(
        ep, 2 * HID, W_post_cat, POOL, hc, POOL, b_post_cat, HID);

    // K2b: tail_cat = edge_rep[:, 512:] @ W_post_cat[512:]
    sgemm_bias<<<dim3(POOL / BN, N_OBJ / BM), 256>>>(
        ep + HID, 2 * HID, W_post_cat + (size_t)HID * POOL, POOL, tc, POOL,
        nullptr, HID);

    // K3: fused gather + elementwise + W_rel GEMM + bias + freq
    fused_rel<<<N_REL / 16, 256>>>(U, hc, tc, W_rel, b_rel, freq,
                                   pair_idx, obj_preds, out);
}

// round 2
// speedup vs baseline: 1.8650x; 1.8650x over previous
#include <cuda_runtime.h>
#include <cuda_bf16.h>
#include <cstdint>

#define HID 512
#define POOL 4096
#define N_OBJ 1280
#define N_REL 16384
#define NUM_OBJ_CLS 151
#define NUM_REL_CLS 51

// -------- scratch (device globals; no allocation allowed) --------
__device__ float g_edge_rep[N_OBJ * 2 * HID];     // 1280 x 1024
__device__ float g_head_cat[N_OBJ * POOL];        // 1280 x 4096 (includes b_post_cat)
__device__ float g_tail_cat[N_OBJ * POOL];        // 1280 x 4096

// =====================================================================
// fp32 SGEMM with optional bias, double-buffered smem.
// C = A @ B (+ bias).  BM=BN=128, BK=8, 256 threads, 8x8 microtile.
// Requires M%128==0, N%128==0, K%8==0.
// =====================================================================
#define BM 128
#define BN 128
#define BKK 8

__global__ __launch_bounds__(256, 2) void sgemm_bias(
    const float* __restrict__ A, int lda,
    const float* __restrict__ B, int ldb,
    float* __restrict__ C, int ldc,
    const float* __restrict__ bias,
    int K)
{
    __shared__ float As[2][BKK][BM];
    __shared__ float Bs[2][BKK][BN];

    const int tid = threadIdx.x;
    const int rowBase = blockIdx.y * BM;
    const int colBase = blockIdx.x * BN;

    const int aRow = tid >> 1;
    const int aCol = (tid & 1) * 4;
    const int bRow = tid >> 5;
    const int bCol = (tid & 31) * 4;

    const float* Aptr = A + (size_t)(rowBase + aRow) * lda + aCol;
    const float* Bptr = B + (size_t)bRow * ldb + colBase + bCol;

    const int tr = tid >> 4;
    const int tc = tid & 15;

    float acc[8][8];
    #pragma unroll
    for (int m = 0; m < 8; m++)
        #pragma unroll
        for (int n = 0; n < 8; n++) acc[m][n] = 0.0f;

    // preload tile 0
    float4 a4 = *(const float4*)(Aptr);
    float4 b4 = *(const float4*)(Bptr);
    As[0][aCol + 0][aRow] = a4.x;
    As[0][aCol + 1][aRow] = a4.y;
    As[0][aCol + 2][aRow] = a4.z;
    As[0][aCol + 3][aRow] = a4.w;
    *(float4*)&Bs[0][bRow][bCol] = b4;
    __syncthreads();

    int buf = 0;
    for (int k0 = 0; k0 < K; k0 += BKK) {
        // issue loads for next tile (if any)
        const bool has_next = (k0 + BKK) < K;
        if (has_next) {
            a4 = *(const float4*)(Aptr + k0 + BKK);
            b4 = *(const float4*)(Bptr + (size_t)(k0 + BKK) * ldb);
        }

        // compute on current buffer
        #pragma unroll
        for (int kk = 0; kk < BKK; kk++) {
            float ra[8], rb[8];
            float4 ra0 = *(const float4*)&As[buf][kk][tr * 8];
            float4 ra1 = *(const float4*)&As[buf][kk][tr * 8 + 4];
            float4 rb0 = *(const float4*)&Bs[buf][kk][tc * 8];
            float4 rb1 = *(const float4*)&Bs[buf][kk][tc * 8 + 4];
            ra[0]=ra0.x; ra[1]=ra0.y; ra[2]=ra0.z; ra[3]=ra0.w;
            ra[4]=ra1.x; ra[5]=ra1.y; ra[6]=ra1.z; ra[7]=ra1.w;
            rb[0]=rb0.x; rb[1]=rb0.y; rb[2]=rb0.z; rb[3]=rb0.w;
            rb[4]=rb1.x; rb[5]=rb1.y; rb[6]=rb1.z; rb[7]=rb1.w;
            #pragma unroll
            for (int m = 0; m < 8; m++)
                #pragma unroll
                for (int n = 0; n < 8; n++)
                    acc[m][n] = fmaf(ra[m], rb[n], acc[m][n]);
        }

        if (has_next) {
            const int nb = buf ^ 1;
            As[nb][aCol + 0][aRow] = a4.x;
            As[nb][aCol + 1][aRow] = a4.y;
            As[nb][aCol + 2][aRow] = a4.z;
            As[nb][aCol + 3][aRow] = a4.w;
            *(float4*)&Bs[nb][bRow][bCol] = b4;
            __syncthreads();
            buf = nb;
        }
    }

    #pragma unroll
    for (int m = 0; m < 8; m++) {
        const int row = rowBase + tr * 8 + m;
        #pragma unroll
        for (int n = 0; n < 8; n += 4) {
            const int col = colBase + tc * 8 + n;
            float4 v;
            v.x = acc[m][n + 0];
            v.y = acc[m][n + 1];
            v.z = acc[m][n + 2];
            v.w = acc[m][n + 3];
            if (bias) {
                v.x += bias[col + 0];
                v.y += bias[col + 1];
                v.z += bias[col + 2];
                v.w += bias[col + 3];
            }
            *(float4*)&C[(size_t)row * ldc + col] = v;
        }
    }
}

// =====================================================================
// Fused epilogue v2: smem-tiled GEMM.
//   A[r,k] = (HC[i_r,k] + TC[j_r,k]) * U[r,k]   (built on the fly into smem)
//   out[r,c] = sum_k A[r,k]*W_rel[k,c] + b_rel[c] + freq[bidx_r, c]
// Tile: 64 rows x 64 cols (51 real) x BK=32. 256 threads, 4x4 microtile.
// =====================================================================
#define FRM 64          // rows per block
#define FBK 32          // k-chunk
#define NPAD 64         // padded col count
#define ASTRIDE 36      // FBK + 4 padding

__global__ __launch_bounds__(256) void fused_rel2(
    const float* __restrict__ U,
    const float* __restrict__ HC,
    const float* __restrict__ TC,
    const float* __restrict__ Wr,     // [4096, 51]
    const float* __restrict__ br,     // [51]
    const float* __restrict__ freq,   // [151*151, 51]
    const int* __restrict__ pair_idx, // [16384, 2]
    const int* __restrict__ obj_preds,// [1280]
    float* __restrict__ out)          // [16384, 51]
{
    __shared__ float Asm[FRM][ASTRIDE];     // A tile, [row][k]
    __shared__ float Wsm[FBK][NPAD];        // W tile, [k][col], cols>=51 are 0
    __shared__ int   sBidx[FRM];

    const int tid = threadIdx.x;
    const int rBase = blockIdx.x * FRM;

    // ---- per-thread staging assignment: fixed row, fixed k-sub-slot ----
    const int sRow = tid >> 2;            // 0..63
    const int sK   = (tid & 3) * 8;       // 0,8,16,24
    const int grow = rBase + sRow;
    const int si = pair_idx[2 * grow];
    const int sj = pair_idx[2 * grow + 1];
    const float* hp = HC + (size_t)si * POOL;
    const float* tp = TC + (size_t)sj * POOL;
    const float* up = U  + (size_t)grow * POOL;

    // bias index per row (threads 0..63), also zero the W pad columns once
    if (tid < FRM) {
        const int r = rBase + tid;
        sBidx[tid] = obj_preds[pair_idx[2 * r]] * NUM_OBJ_CLS
                   + obj_preds[pair_idx[2 * r + 1]];
    }
    for (int idx = tid; idx < FBK * (NPAD - NUM_REL_CLS); idx += 256) {
        const int k = idx / (NPAD - NUM_REL_CLS);
        const int c = NUM_REL_CLS + idx % (NPAD - NUM_REL_CLS);
        Wsm[k][c] = 0.0f;
    }

    // ---- compute assignment ----
    const int tr = tid >> 4;              // 0..15 -> rows tr*4..tr*4+3
    const int tc = tid & 15;              // 0..15 -> cols tc*4..tc*4+3
    const int tr4 = tr * 4;
    const int tc4 = tc * 4;

    float acc[4][4];
    #pragma unroll
    for (int m = 0; m < 4; m++)
        #pragma unroll
        for (int n = 0; n < 4; n++) acc[m][n] = 0.0f;

    for (int k0 = 0; k0 < POOL; k0 += FBK) {
        __syncthreads();   // previous compute finished reading smem

        // stage A: m = (hc + tc) * u  for this thread's (row, 8 k values)
        {
            const float4 h0 = *(const float4*)(hp + k0 + sK);
            const float4 h1 = *(const float4*)(hp + k0 + sK + 4);
            const float4 t0 = *(const float4*)(tp + k0 + sK);
            const float4 t1 = *(const float4*)(tp + k0 + sK + 4);
            const float4 u0 = *(const float4*)(up + k0 + sK);
            const float4 u1 = *(const float4*)(up + k0 + sK + 4);
            float4 m0, m1;
            m0.x = (h0.x + t0.x) * u0.x;
            m0.y = (h0.y + t0.y) * u0.y;
            m0.z = (h0.z + t0.z) * u0.z;
            m0.w = (h0.w + t0.w) * u0.w;
            m1.x = (h1.x + t1.x) * u1.x;
            m1.y = (h1.y + t1.y) * u1.y;
            m1.z = (h1.z + t1.z) * u1.z;
            m1.w = (h1.w + t1.w) * u1.w;
            *(float4*)&Asm[sRow][sK]     = m0;
            *(float4*)&Asm[sRow][sK + 4] = m1;
        }

        // stage W chunk: 32 x 51 contiguous floats from Wr
        {
            const float* src = Wr + (size_t)k0 * NUM_REL_CLS;
            #pragma unroll
            for (int t = 0; t < 7; t++) {
                const int idx = tid + t * 256;
                if (idx < FBK * NUM_REL_CLS) {
                    const int k = idx / NUM_REL_CLS;
                    const int c = idx % NUM_REL_CLS;
                    Wsm[k][c] = src[idx];
                }
            }
        }

        __syncthreads();

        // compute
        #pragma unroll 8
        for (int kk = 0; kk < FBK; kk++) {
            const float a0 = Asm[tr4 + 0][kk];
            const float a1 = Asm[tr4 + 1][kk];
            const float a2 = Asm[tr4 + 2][kk];
            const float a3 = Asm[tr4 + 3][kk];
            const float4 b = *(const float4*)&Wsm[kk][tc4];
            acc[0][0] = fmaf(a0, b.x, acc[0][0]);
            acc[0][1] = fmaf(a0, b.y, acc[0][1]);
            acc[0][2] = fmaf(a0, b.z, acc[0][2]);
            acc[0][3] = fmaf(a0, b.w, acc[0][3]);
            acc[1][0] = fmaf(a1, b.x, acc[1][0]);
            acc[1][1] = fmaf(a1, b.y, acc[1][1]);
            acc[1][2] = fmaf(a1, b.z, acc[1][2]);
            acc[1][3] = fmaf(a1, b.w, acc[1][3]);
            acc[2][0] = fmaf(a2, b.x, acc[2][0]);
            acc[2][1] = fmaf(a2, b.y, acc[2][1]);
            acc[2][2] = fmaf(a2, b.z, acc[2][2]);
            acc[2][3] = fmaf(a2, b.w, acc[2][3]);
            acc[3][0] = fmaf(a3, b.x, acc[3][0]);
            acc[3][1] = fmaf(a3, b.y, acc[3][1]);
            acc[3][2] = fmaf(a3, b.z, acc[3][2]);
            acc[3][3] = fmaf(a3, b.w, acc[3][3]);
        }
    }

    // epilogue: bias + freq gather, write cols < 51
    #pragma unroll
    for (int m = 0; m < 4; m++) {
        const int row = rBase + tr4 + m;
        const int bi = sBidx[tr4 + m];
        const float* fq = freq + (size_t)bi * NUM_REL_CLS;
        float* orow = out + (size_t)row * NUM_REL_CLS;
        #pragma unroll
        for (int n = 0; n < 4; n++) {
            const int c = tc4 + n;
            if (c < NUM_REL_CLS) {
                orow[c] = acc[m][n] + br[c] + fq[c];
            }
        }
    }
}

// =====================================================================
// Launch
// =====================================================================
extern "C" void kernel_launch(void* const* d_in, const int* in_sizes, int n_in,
                              void* d_out, int out_size)
{
    const float* edge_ctx   = (const float*)d_in[0];  // [1280, 512]
    const float* U          = (const float*)d_in[1];  // [16384, 4096]
    const float* W_post_emb = (const float*)d_in[2];  // [512, 1024]
    const float* b_post_emb = (const float*)d_in[3];  // [1024]
    const float* W_post_cat = (const float*)d_in[4];  // [1024, 4096]
    const float* b_post_cat = (const float*)d_in[5];  // [4096]
    const float* W_rel      = (const float*)d_in[6];  // [4096, 51]
    const float* b_rel      = (const float*)d_in[7];  // [51]
    const float* freq       = (const float*)d_in[8];  // [151*151, 51]
    const int*   pair_idx   = (const int*)d_in[9];    // [16384, 2]
    const int*   obj_preds  = (const int*)d_in[10];   // [1280]
    float* out = (float*)d_out;

    float *ep, *hc, *tc;
    cudaGetSymbolAddress((void**)&ep, g_edge_rep);
    cudaGetSymbolAddress((void**)&hc, g_head_cat);
    cudaGetSymbolAddress((void**)&tc, g_tail_cat);

    // K1: edge_rep = edge_ctx @ W_post_emb + b_post_emb    [1280 x 1024]
    sgemm_bias<<<dim3((2 * HID) / BN, N_OBJ / BM), 256>>>(
        edge_ctx, HID, W_post_emb, 2 * HID, ep, 2 * HID, b_post_emb, HID);

    // K2a: head_cat = edge_rep[:, :512] @ W_post_cat[:512] + b_post_cat
    sgemm_bias<<<dim3(POOL / BN, N_OBJ / BM), 256>>>(
        ep, 2 * HID, W_post_cat, POOL, hc, POOL, b_post_cat, HID);

    // K2b: tail_cat = edge_rep[:, 512:] @ W_post_cat[512:]
    sgemm_bias<<<dim3(POOL / BN, N_OBJ / BM), 256>>>(
        ep + HID, 2 * HID, W_post_cat + (size_t)HID * POOL, POOL, tc, POOL,
        nullptr, HID);

    // K3: fused gather + elementwise + W_rel GEMM + bias + freq
    fused_rel2<<<N_REL / FRM, 256>>>(U, hc, tc, W_rel, b_rel, freq,
                                     pair_idx, obj_preds, out);
}

// round 4
// speedup vs baseline: 1.9354x; 1.0378x over previous
#include <cuda_runtime.h>
#include <cuda_bf16.h>
#include <cstdint>

#define HID 512
#define POOL 4096
#define N_OBJ 1280
#define N_REL 16384
#define NUM_OBJ_CLS 151
#define NUM_REL_CLS 51

// fused_rel tiling
#define FRM 64          // rows per block
#define FBK 32          // k-chunk
#define NPAD 64         // padded col count
#define SPLITK 4
#define KSPLIT (POOL / SPLITK)   // 1024
#define ASTR 68         // k-major A tile stride (mult of 4 -> aligned LDS.128)

// -------- scratch (device globals; no allocation allowed) --------
__device__ float g_edge_rep[N_OBJ * 2 * HID];        // 1280 x 1024
__device__ float g_head_cat[N_OBJ * POOL];           // includes b_post_cat
__device__ float g_tail_cat[N_OBJ * POOL];
__device__ float g_part[SPLITK * N_REL * NPAD];      // split-K partials (16.8MB)

// =====================================================================
// fp32 GEMM core: BM=128, BN=64, BK=8, 256 threads, 8x4 microtile,
// double-buffered smem. Requires M%128==0, N%64==0, K%8==0.
// =====================================================================
#define GBM 128
#define GBN 64
#define GBK 8
#define ASTR_G 132   // padded As row stride (kills STS 2-way conflict)

__device__ __forceinline__ void gemm_body(
    const float* __restrict__ A, int lda,
    const float* __restrict__ B, int ldb,
    float* __restrict__ C, int ldc,
    const float* __restrict__ bias,
    int K, int rowBase, int colBase)
{
    __shared__ float As[2][GBK][ASTR_G];
    __shared__ float Bs[2][GBK][GBN];

    const int tid = threadIdx.x;

    const int aRow = tid >> 1;            // 0..127
    const int aCol = (tid & 1) * 4;       // 0 or 4
    const int bRow = tid >> 5;            // 0..7
    const int bCol = (tid & 31) * 2;      // 0..62

    const float* Aptr = A + (size_t)(rowBase + aRow) * lda + aCol;
    const float* Bptr = B + (size_t)bRow * ldb + colBase + bCol;

    const int tr = tid >> 4;              // 0..15 -> rows tr*8
    const int tc = tid & 15;              // 0..15 -> cols tc*4
    const int tr8 = tr * 8;
    const int tc4 = tc * 4;

    float acc[8][4];
    #pragma unroll
    for (int m = 0; m < 8; m++)
        #pragma unroll
        for (int n = 0; n < 4; n++) acc[m][n] = 0.0f;

    float4 a4 = *(const float4*)(Aptr);
    float2 b2 = *(const float2*)(Bptr);
    As[0][aCol + 0][aRow] = a4.x;
    As[0][aCol + 1][aRow] = a4.y;
    As[0][aCol + 2][aRow] = a4.z;
    As[0][aCol + 3][aRow] = a4.w;
    *(float2*)&Bs[0][bRow][bCol] = b2;
    __syncthreads();

    int buf = 0;
    for (int k0 = 0; k0 < K; k0 += GBK) {
        const bool has_next = (k0 + GBK) < K;
        if (has_next) {
            a4 = *(const float4*)(Aptr + k0 + GBK);
            b2 = *(const float2*)(Bptr + (size_t)(k0 + GBK) * ldb);
        }

        #pragma unroll
        for (int kk = 0; kk < GBK; kk++) {
            float4 ra0 = *(const float4*)&As[buf][kk][tr8];
            float4 ra1 = *(const float4*)&As[buf][kk][tr8 + 4];
            float4 rb  = *(const float4*)&Bs[buf][kk][tc4];
            float ra[8] = {ra0.x, ra0.y, ra0.z, ra0.w, ra1.x, ra1.y, ra1.z, ra1.w};
            float rbv[4] = {rb.x, rb.y, rb.z, rb.w};
            #pragma unroll
            for (int m = 0; m < 8; m++)
                #pragma unroll
                for (int n = 0; n < 4; n++)
                    acc[m][n] = fmaf(ra[m], rbv[n], acc[m][n]);
        }

        if (has_next) {
            const int nb = buf ^ 1;
            As[nb][aCol + 0][aRow] = a4.x;
            As[nb][aCol + 1][aRow] = a4.y;
            As[nb][aCol + 2][aRow] = a4.z;
            As[nb][aCol + 3][aRow] = a4.w;
            *(float2*)&Bs[nb][bRow][bCol] = b2;
            __syncthreads();
            buf = nb;
        }
    }

    #pragma unroll
    for (int m = 0; m < 8; m++) {
        const int row = rowBase + tr8 + m;
        const int col = colBase + tc4;
        float4 v;
        v.x = acc[m][0]; v.y = acc[m][1]; v.z = acc[m][2]; v.w = acc[m][3];
        if (bias) {
            v.x += bias[col + 0];
            v.y += bias[col + 1];
            v.z += bias[col + 2];
            v.w += bias[col + 3];
        }
        *(float4*)&C[(size_t)row * ldc + col] = v;
    }
}

// K1: edge_rep = edge_ctx @ W_post_emb + b_post_emb
__global__ __launch_bounds__(256, 2) void k1_gemm(
    const float* __restrict__ A, const float* __restrict__ B,
    const float* __restrict__ bias, float* __restrict__ C)
{
    gemm_body(A, HID, B, 2 * HID, C, 2 * HID, bias,
              HID, blockIdx.y * GBM, blockIdx.x * GBN);
}

// K2 merged: z=0 -> head_cat (+b_post_cat), z=1 -> tail_cat
__global__ __launch_bounds__(256, 2) void k2_gemm(
    const float* __restrict__ ep, const float* __restrict__ W,
    const float* __restrict__ bpc,
    float* __restrict__ hc, float* __restrict__ tcat)
{
    if (blockIdx.z == 0) {
        gemm_body(ep, 2 * HID, W, POOL, hc, POOL, bpc,
                  HID, blockIdx.y * GBM, blockIdx.x * GBN);
    } else {
        gemm_body(ep + HID, 2 * HID, W + (size_t)HID * POOL, POOL, tcat, POOL,
                  nullptr, HID, blockIdx.y * GBM, blockIdx.x * GBN);
    }
}

// =====================================================================
// fused_rel3: split-K GEMM producing fp32 partials.
//   A[r,k] = (HC[i_r,k] + TC[j_r,k]) * U[r,k]   built on-the-fly into smem
//   part[sp,r,c] = sum_{k in split sp} A[r,k] * W_rel[k,c]
// A tile stored k-major [FBK][ASTR]; compute reads A as broadcast float4.
// Staging map: lane-distinct rows -> conflict-free scalar STS for any ASTR.
// =====================================================================
__global__ __launch_bounds__(256) void fused_rel3(
    const float* __restrict__ U,
    const float* __restrict__ HC,
    const float* __restrict__ TC,
    const float* __restrict__ Wr,     // [4096, 51]
    const int* __restrict__ pair_idx, // [16384, 2]
    float* __restrict__ part)         // [SPLITK, N_REL, NPAD]
{
    __shared__ float Asm[FBK][ASTR];        // [k][row], 32 x 68
    __shared__ float Wsm[FBK][NPAD];        // [k][col], cols >= 51 zero

    const int tid = threadIdx.x;
    const int rBase = blockIdx.x * FRM;
    const int sp = blockIdx.y;
    const int kb = sp * KSPLIT;

    // staging: row = tid & 63 (lane-distinct), k slot = (tid >> 6) * 8
    const int sRow = tid & 63;             // 0..63
    const int sK   = (tid >> 6) * 8;       // 0,8,16,24
    const int grow = rBase + sRow;
    const int si = pair_idx[2 * grow];
    const int sj = pair_idx[2 * grow + 1];
    const float* hp = HC + (size_t)si * POOL + kb;
    const float* tp = TC + (size_t)sj * POOL + kb;
    const float* up = U  + (size_t)grow * POOL + kb;
    const float* wp = Wr + (size_t)kb * NUM_REL_CLS;

    // zero W pad columns once
    for (int idx = tid; idx < FBK * (NPAD - NUM_REL_CLS); idx += 256) {
        const int k = idx / (NPAD - NUM_REL_CLS);
        const int c = NUM_REL_CLS + idx % (NPAD - NUM_REL_CLS);
        Wsm[k][c] = 0.0f;
    }

    const int tr4 = (tid >> 4) * 4;
    const int tc4 = (tid & 15) * 4;

    float acc[4][4];
    #pragma unroll
    for (int m = 0; m < 4; m++)
        #pragma unroll
        for (int n = 0; n < 4; n++) acc[m][n] = 0.0f;

    for (int k0 = 0; k0 < KSPLIT; k0 += FBK) {
        __syncthreads();

        // stage A: (hc + tc) * u, written k-major
        {
            const float4 h0 = *(const float4*)(hp + k0 + sK);
            const float4 h1 = *(const float4*)(hp + k0 + sK + 4);
            const float4 t0 = *(const float4*)(tp + k0 + sK);
            const float4 t1 = *(const float4*)(tp + k0 + sK + 4);
            const float4 u0 = *(const float4*)(up + k0 + sK);
            const float4 u1 = *(const float4*)(up + k0 + sK + 4);
            Asm[sK + 0][sRow] = (h0.x + t0.x) * u0.x;
            Asm[sK + 1][sRow] = (h0.y + t0.y) * u0.y;
            Asm[sK + 2][sRow] = (h0.z + t0.z) * u0.z;
            Asm[sK + 3][sRow] = (h0.w + t0.w) * u0.w;
            Asm[sK + 4][sRow] = (h1.x + t1.x) * u1.x;
            Asm[sK + 5][sRow] = (h1.y + t1.y) * u1.y;
            Asm[sK + 6][sRow] = (h1.z + t1.z) * u1.z;
            Asm[sK + 7][sRow] = (h1.w + t1.w) * u1.w;
        }

        // stage W chunk: 32 x 51 contiguous
        {
            const float* src = wp + (size_t)k0 * NUM_REL_CLS;
            #pragma unroll
            for (int t = 0; t < 7; t++) {
                const int idx = tid + t * 256;
                if (idx < FBK * NUM_REL_CLS) {
                    Wsm[idx / NUM_REL_CLS][idx % NUM_REL_CLS] = src[idx];
                }
            }
        }

        __syncthreads();

        #pragma unroll 8
        for (int kk = 0; kk < FBK; kk++) {
            const float4 a = *(const float4*)&Asm[kk][tr4];
            const float4 b = *(const float4*)&Wsm[kk][tc4];
            acc[0][0] = fmaf(a.x, b.x, acc[0][0]);
            acc[0][1] = fmaf(a.x, b.y, acc[0][1]);
            acc[0][2] = fmaf(a.x, b.z, acc[0][2]);
            acc[0][3] = fmaf(a.x, b.w, acc[0][3]);
            acc[1][0] = fmaf(a.y, b.x, acc[1][0]);
            acc[1][1] = fmaf(a.y, b.y, acc[1][1]);
            acc[1][2] = fmaf(a.y, b.z, acc[1][2]);
            acc[1][3] = fmaf(a.y, b.w, acc[1][3]);
            acc[2][0] = fmaf(a.z, b.x, acc[2][0]);
            acc[2][1] = fmaf(a.z, b.y, acc[2][1]);
            acc[2][2] = fmaf(a.z, b.z, acc[2][2]);
            acc[2][3] = fmaf(a.z, b.w, acc[2][3]);
            acc[3][0] = fmaf(a.w, b.x, acc[3][0]);
            acc[3][1] = fmaf(a.w, b.y, acc[3][1]);
            acc[3][2] = fmaf(a.w, b.z, acc[3][2]);
            acc[3][3] = fmaf(a.w, b.w, acc[3][3]);
        }
    }

    float* pbase = part + ((size_t)sp * N_REL + rBase) * NPAD;
    #pragma unroll
    for (int m = 0; m < 4; m++) {
        float4 v;
        v.x = acc[m][0]; v.y = acc[m][1]; v.z = acc[m][2]; v.w = acc[m][3];
        *(float4*)&pbase[(size_t)(tr4 + m) * NPAD + tc4] = v;
    }
}

// =====================================================================
// combine: out[r,c] = sum_sp part[sp,r,c] + b_rel[c] + freq[bidx_r,c]
// 256 threads = 4 rows x 64 lanes.
// =====================================================================
__global__ __launch_bounds__(256) void combine_rel(
    const float* __restrict__ part,
    const float* __restrict__ br,
    const float* __restrict__ freq,
    const int* __restrict__ pair_idx,
    const int* __restrict__ obj_preds,
    float* __restrict__ out)
{
    const int r = blockIdx.x * 4 + (threadIdx.x >> 6);
    const int c = threadIdx.x & 63;
    if (c >= NUM_REL_CLS) return;

    const int bi = obj_preds[pair_idx[2 * r]] * NUM_OBJ_CLS
                 + obj_preds[pair_idx[2 * r + 1]];

    float s = 0.0f;
    #pragma unroll
    for (int sp = 0; sp < SPLITK; sp++)
        s += part[((size_t)sp * N_REL + r) * NPAD + c];

    out[(size_t)r * NUM_REL_CLS + c] = s + br[c] + freq[(size_t)bi * NUM_REL_CLS + c];
}

// =====================================================================
// Launch
// =====================================================================
extern "C" void kernel_launch(void* const* d_in, const int* in_sizes, int n_in,
                              void* d_out, int out_size)
{
    const float* edge_ctx   = (const float*)d_in[0];
    const float* U          = (const float*)d_in[1];
    const float* W_post_emb = (const float*)d_in[2];
    const float* b_post_emb = (const float*)d_in[3];
    const float* W_post_cat = (const float*)d_in[4];
    const float* b_post_cat = (const float*)d_in[5];
    const float* W_rel      = (const float*)d_in[6];
    const float* b_rel      = (const float*)d_in[7];
    const float* freq       = (const float*)d_in[8];
    const int*   pair_idx   = (const int*)d_in[9];
    const int*   obj_preds  = (const int*)d_in[10];
    float* out = (float*)d_out;

    float *ep, *hc, *tc, *part;
    cudaGetSymbolAddress((void**)&ep, g_edge_rep);
    cudaGetSymbolAddress((void**)&hc, g_head_cat);
    cudaGetSymbolAddress((void**)&tc, g_tail_cat);
    cudaGetSymbolAddress((void**)&part, g_part);

    // K1: edge_rep = edge_ctx @ W_post_emb + b_post_emb   [1280 x 1024]
    k1_gemm<<<dim3((2 * HID) / GBN, N_OBJ / GBM), 256>>>(
        edge_ctx, W_post_emb, b_post_emb, ep);

    // K2 (merged): head_cat / tail_cat                     [1280 x 4096] x2
    k2_gemm<<<dim3(POOL / GBN, N_OBJ / GBM, 2), 256>>>(
        ep, W_post_cat, b_post_cat, hc, tc);

    // K3: split-K fused GEMM -> partials
    fused_rel3<<<dim3(N_REL / FRM, SPLITK), 256>>>(
        U, hc, tc, W_rel, pair_idx, part);

    // K4: combine partials + bias + freq gather
    combine_rel<<<N_REL / 4, 256>>>(part, b_rel, freq, pair_idx, obj_preds, out);
}

// round 6
// speedup vs baseline: 2.4285x; 1.2547x over previous
#include <cuda_runtime.h>
#include <cuda_bf16.h>
#include <cstdint>

#define HID 512
#define POOL 4096
#define N_OBJ 1280
#define N_REL 16384
#define NUM_OBJ_CLS 151
#define NUM_REL_CLS 51

// fused_rel tiling (unchanged, passing)
#define FRM 64
#define FBK 32
#define NPAD 64
#define SPLITK 4
#define KSPLIT (POOL / SPLITK)
#define ASTR 68

// -------- scratch (device globals; no allocation allowed) --------
__device__ float g_edge_rep[N_OBJ * 2 * HID];
__device__ float g_head_cat[N_OBJ * POOL];
__device__ float g_tail_cat[N_OBJ * POOL];
__device__ float g_part[SPLITK * N_REL * NPAD];
__device__ __nv_bfloat16 g_A_hi[N_OBJ * 2 * HID];
__device__ __nv_bfloat16 g_A_lo[N_OBJ * 2 * HID];
__device__ __nv_bfloat16 g_Bt_hi[POOL * 2 * HID];    // W_post_cat^T
__device__ __nv_bfloat16 g_Bt_lo[POOL * 2 * HID];

// =====================================================================
// helpers
// =====================================================================
__device__ __forceinline__ uint32_t smem_u32(const void* p) {
    uint32_t a;
    asm("{ .reg .u64 t; cvta.to.shared.u64 t, %1; cvt.u32.u64 %0, t; }"
        : "=r"(a) : "l"(p));
    return a;
}
#define SWZ128(off) ((off) ^ (((off) >> 3) & 0x70))

__device__ __forceinline__ void ldsm_x4(uint32_t* r, uint32_t addr) {
    asm volatile("ldmatrix.sync.aligned.m8n8.x4.shared.b16 {%0,%1,%2,%3}, [%4];"
                 : "=r"(r[0]), "=r"(r[1]), "=r"(r[2]), "=r"(r[3]) : "r"(addr));
}

__device__ __forceinline__ void mma_bf16(float* d, const uint32_t* a, const uint32_t* b) {
    asm volatile(
        "mma.sync.aligned.m16n8k16.row.col.f32.bf16.bf16.f32 "
        "{%0,%1,%2,%3}, {%4,%5,%6,%7}, {%8,%9}, {%0,%1,%2,%3};"
        : "+f"(d[0]), "+f"(d[1]), "+f"(d[2]), "+f"(d[3])
        : "r"(a[0]), "r"(a[1]), "r"(a[2]), "r"(a[3]), "r"(b[0]), "r"(b[1]));
}

// =====================================================================
// Pre-split kernels (unchanged)
// =====================================================================
__global__ __launch_bounds__(256) void split_A(
    const float* __restrict__ src, __nv_bfloat16* __restrict__ hi,
    __nv_bfloat16* __restrict__ lo, int n)
{
    int i = blockIdx.x * 256 + threadIdx.x;
    if (i >= n) return;
    float x = src[i];
    __nv_bfloat16 h = __float2bfloat16(x);
    hi[i] = h;
    lo[i] = __float2bfloat16(x - __bfloat162float(h));
}

__global__ __launch_bounds__(256) void transpose_split_B(
    const float* __restrict__ W,
    __nv_bfloat16* __restrict__ bhi, __nv_bfloat16* __restrict__ blo)
{
    __shared__ float t[32][33];
    const int kb = blockIdx.y * 32;
    const int nb = blockIdx.x * 32;
    const int tx = threadIdx.x & 31;
    const int ty = threadIdx.x >> 5;
    #pragma unroll
    for (int s = 0; s < 4; s++) {
        const int k = kb + ty + s * 8;
        t[ty + s * 8][tx] = W[(size_t)k * POOL + nb + tx];
    }
    __syncthreads();
    #pragma unroll
    for (int s = 0; s < 4; s++) {
        const int n = nb + ty + s * 8;
        const float x = t[tx][ty + s * 8];
        __nv_bfloat16 h = __float2bfloat16(x);
        const size_t o = (size_t)n * (2 * HID) + kb + tx;
        bhi[o] = h;
        blo[o] = __float2bfloat16(x - __bfloat162float(h));
    }
}

// =====================================================================
// K2 via mma.sync (HMMA) bf16 split-precision.
// Block: 256 thr = 8 warps (4 m x 2 n), tile M=128 N=64, K=512, BK=64.
// smem: A_hi 16K | A_lo 16K | B_hi 8K | B_lo 8K  (SW128, 128B rows) = 48KB
// grid (POOL/64, N_OBJ/128, 2): z=0 head(+bias), z=1 tail.
// =====================================================================
#define K2_BK 64
#define S_AHI 0
#define S_ALO 16384
#define S_BHI 32768
#define S_BLO 40960

__global__ __launch_bounds__(256) void k2_hmma(
    const __nv_bfloat16* __restrict__ Ahi, const __nv_bfloat16* __restrict__ Alo,
    const __nv_bfloat16* __restrict__ Bhi, const __nv_bfloat16* __restrict__ Blo,
    const float* __restrict__ bpc,
    float* __restrict__ hc, float* __restrict__ tcat)
{
    __shared__ char smem[49152];
    const uint32_t sb = smem_u32(smem);
    const int tid = threadIdx.x;
    const int wid = tid >> 5;
    const int lane = tid & 31;
    const int bx = blockIdx.x;
    const int by = blockIdx.y;
    const int z = blockIdx.z;
    const int koff = z * HID;

    const int m0 = (wid >> 1) * 32;     // warp m offset in tile
    const int n0 = (wid & 1) * 32;      // warp n offset in tile

    float acc[2][4][4];
    #pragma unroll
    for (int mf = 0; mf < 2; mf++)
        #pragma unroll
        for (int nf = 0; nf < 4; nf++)
            #pragma unroll
            for (int e = 0; e < 4; e++) acc[mf][nf][e] = 0.0f;

    // chunk-invariant pieces of the ldmatrix addresses
    // A: row = m0 + mf*16 + (lane&15); colByte = kk*2 + ((lane&16)?16:0)
    const int aRowOff = (m0 + (lane & 15)) * 128 + ((lane & 16) ? 16 : 0);
    // B: row = n0 + nf2*16 + (lane&7) + ((lane&16)?8:0); colByte = kk*2 + ((lane&8)?16:0)
    const int bRowOff = (n0 + (lane & 7) + ((lane & 16) ? 8 : 0)) * 128 + ((lane & 8) ? 16 : 0);

    for (int ch = 0; ch < HID / K2_BK; ch++) {
        const int k0 = koff + ch * K2_BK;
        __syncthreads();

        // stage A: 128 rows x 64 bf16 (hi+lo), SW128 on 128B rows
        #pragma unroll
        for (int g = tid; g < 1024; g += 256) {
            const int row = g >> 3, grp = g & 7;
            const size_t src = (size_t)(by * 128 + row) * (2 * HID) + k0 + grp * 8;
            const uint32_t dst = SWZ128((uint32_t)(row * 128 + grp * 16));
            *(uint4*)(smem + S_AHI + dst) = *(const uint4*)(Ahi + src);
            *(uint4*)(smem + S_ALO + dst) = *(const uint4*)(Alo + src);
        }
        // stage B: 64 rows x 64 bf16 (hi+lo)
        #pragma unroll
        for (int g = tid; g < 512; g += 256) {
            const int row = g >> 3, grp = g & 7;
            const size_t src = (size_t)(bx * 64 + row) * (2 * HID) + k0 + grp * 8;
            const uint32_t dst = SWZ128((uint32_t)(row * 128 + grp * 16));
            *(uint4*)(smem + S_BHI + dst) = *(const uint4*)(Bhi + src);
            *(uint4*)(smem + S_BLO + dst) = *(const uint4*)(Blo + src);
        }
        __syncthreads();

        #pragma unroll
        for (int kk = 0; kk < K2_BK; kk += 16) {
            uint32_t ahi[2][4], alo[2][4], bh[2][4], bl[2][4];
            #pragma unroll
            for (int mf = 0; mf < 2; mf++) {
                const uint32_t off = SWZ128((uint32_t)(aRowOff + mf * 16 * 128 + kk * 2));
                ldsm_x4(ahi[mf], sb + S_AHI + off);
                ldsm_x4(alo[mf], sb + S_ALO + off);
            }
            #pragma unroll
            for (int nf2 = 0; nf2 < 2; nf2++) {
                const uint32_t off = SWZ128((uint32_t)(bRowOff + nf2 * 16 * 128 + kk * 2));
                ldsm_x4(bh[nf2], sb + S_BHI + off);
                ldsm_x4(bl[nf2], sb + S_BLO + off);
            }
            #pragma unroll
            for (int mf = 0; mf < 2; mf++) {
                #pragma unroll
                for (int nf = 0; nf < 4; nf++) {
                    const uint32_t* bhp = &bh[nf >> 1][(nf & 1) * 2];
                    const uint32_t* blp = &bl[nf >> 1][(nf & 1) * 2];
                    mma_bf16(acc[mf][nf], ahi[mf], bhp);
                    mma_bf16(acc[mf][nf], ahi[mf], blp);
                    mma_bf16(acc[mf][nf], alo[mf], bhp);
                }
            }
        }
    }

    // epilogue: d0,d1 -> (row, col..col+1); d2,d3 -> (row+8, col..col+1)
    const int gm = by * 128 + m0 + (lane >> 2);
    const int gn = bx * 64 + n0 + (lane & 3) * 2;
    float* Cb = (z == 0 ? hc : tcat);
    #pragma unroll
    for (int mf = 0; mf < 2; mf++) {
        #pragma unroll
        for (int nf = 0; nf < 4; nf++) {
            const int col = gn + nf * 8;
            float b0 = 0.0f, b1 = 0.0f;
            if (z == 0) { b0 = bpc[col]; b1 = bpc[col + 1]; }
            const int r0 = gm + mf * 16;
            float2 v0, v1;
            v0.x = acc[mf][nf][0] + b0;
            v0.y = acc[mf][nf][1] + b1;
            v1.x = acc[mf][nf][2] + b0;
            v1.y = acc[mf][nf][3] + b1;
            *(float2*)&Cb[(size_t)r0 * POOL + col] = v0;
            *(float2*)&Cb[(size_t)(r0 + 8) * POOL + col] = v1;
        }
    }
}

// =====================================================================
// fp32 GEMM (K1): BM=128, BN=64, BK=8, 256 thr, 8x4 microtile.
// =====================================================================
#define GBM 128
#define GBN 64
#define GBK 8
#define ASTR_G 132

__global__ __launch_bounds__(256, 2) void k1_gemm(
    const float* __restrict__ A, const float* __restrict__ B,
    const float* __restrict__ bias, float* __restrict__ C)
{
    __shared__ float As[2][GBK][ASTR_G];
    __shared__ float Bs[2][GBK][GBN];

    const int tid = threadIdx.x;
    const int rowBase = blockIdx.y * GBM;
    const int colBase = blockIdx.x * GBN;
    const int lda = HID, ldb = 2 * HID, ldc = 2 * HID, K = HID;

    const int aRow = tid >> 1;
    const int aCol = (tid & 1) * 4;
    const int bRow = tid >> 5;
    const int bCol = (tid & 31) * 2;

    const float* Aptr = A + (size_t)(rowBase + aRow) * lda + aCol;
    const float* Bptr = B + (size_t)bRow * ldb + colBase + bCol;

    const int tr8 = (tid >> 4) * 8;
    const int tc4 = (tid & 15) * 4;

    float acc[8][4];
    #pragma unroll
    for (int m = 0; m < 8; m++)
        #pragma unroll
        for (int n = 0; n < 4; n++) acc[m][n] = 0.0f;

    float4 a4 = *(const float4*)(Aptr);
    float2 b2 = *(const float2*)(Bptr);
    As[0][aCol + 0][aRow] = a4.x;
    As[0][aCol + 1][aRow] = a4.y;
    As[0][aCol + 2][aRow] = a4.z;
    As[0][aCol + 3][aRow] = a4.w;
    *(float2*)&Bs[0][bRow][bCol] = b2;
    __syncthreads();

    int buf = 0;
    for (int k0 = 0; k0 < K; k0 += GBK) {
        const bool has_next = (k0 + GBK) < K;
        if (has_next) {
            a4 = *(const float4*)(Aptr + k0 + GBK);
            b2 = *(const float2*)(Bptr + (size_t)(k0 + GBK) * ldb);
        }
        #pragma unroll
        for (int kk = 0; kk < GBK; kk++) {
            float4 ra0 = *(const float4*)&As[buf][kk][tr8];
            float4 ra1 = *(const float4*)&As[buf][kk][tr8 + 4];
            float4 rb  = *(const float4*)&Bs[buf][kk][tc4];
            float ra[8] = {ra0.x, ra0.y, ra0.z, ra0.w, ra1.x, ra1.y, ra1.z, ra1.w};
            float rbv[4] = {rb.x, rb.y, rb.z, rb.w};
            #pragma unroll
            for (int m = 0; m < 8; m++)
                #pragma unroll
                for (int n = 0; n < 4; n++)
                    acc[m][n] = fmaf(ra[m], rbv[n], acc[m][n]);
        }
        if (has_next) {
            const int nb = buf ^ 1;
            As[nb][aCol + 0][aRow] = a4.x;
            As[nb][aCol + 1][aRow] = a4.y;
            As[nb][aCol + 2][aRow] = a4.z;
            As[nb][aCol + 3][aRow] = a4.w;
            *(float2*)&Bs[nb][bRow][bCol] = b2;
            __syncthreads();
            buf = nb;
        }
    }

    #pragma unroll
    for (int m = 0; m < 8; m++) {
        const int row = rowBase + tr8 + m;
        const int col = colBase + tc4;
        float4 v;
        v.x = acc[m][0] + bias[col + 0];
        v.y = acc[m][1] + bias[col + 1];
        v.z = acc[m][2] + bias[col + 2];
        v.w = acc[m][3] + bias[col + 3];
        *(float4*)&C[(size_t)row * ldc + col] = v;
    }
}

// =====================================================================
// fused_rel3 (unchanged, passing)
// =====================================================================
__global__ __launch_bounds__(256) void fused_rel3(
    const float* __restrict__ U,
    const float* __restrict__ HC,
    const float* __restrict__ TC,
    const float* __restrict__ Wr,
    const int* __restrict__ pair_idx,
    float* __restrict__ part)
{
    __shared__ float Asm[FBK][ASTR];
    __shared__ float Wsm[FBK][NPAD];

    const int tid = threadIdx.x;
    const int rBase = blockIdx.x * FRM;
    const int sp = blockIdx.y;
    const int kb = sp * KSPLIT;

    const int sRow = tid & 63;
    const int sK   = (tid >> 6) * 8;
    const int grow = rBase + sRow;
    const int si = pair_idx[2 * grow];
    const int sj = pair_idx[2 * grow + 1];
    const float* hp = HC + (size_t)si * POOL + kb;
    const float* tp = TC + (size_t)sj * POOL + kb;
    const float* up = U  + (size_t)grow * POOL + kb;
    const float* wp = Wr + (size_t)kb * NUM_REL_CLS;

    for (int idx = tid; idx < FBK * (NPAD - NUM_REL_CLS); idx += 256) {
        const int k = idx / (NPAD - NUM_REL_CLS);
        const int c = NUM_REL_CLS + idx % (NPAD - NUM_REL_CLS);
        Wsm[k][c] = 0.0f;
    }

    const int tr4 = (tid >> 4) * 4;
    const int tc4 = (tid & 15) * 4;

    float acc[4][4];
    #pragma unroll
    for (int m = 0; m < 4; m++)
        #pragma unroll
        for (int n = 0; n < 4; n++) acc[m][n] = 0.0f;

    for (int k0 = 0; k0 < KSPLIT; k0 += FBK) {
        __syncthreads();
        {
            const float4 h0 = *(const float4*)(hp + k0 + sK);
            const float4 h1 = *(const float4*)(hp + k0 + sK + 4);
            const float4 t0 = *(const float4*)(tp + k0 + sK);
            const float4 t1 = *(const float4*)(tp + k0 + sK + 4);
            const float4 u0 = *(const float4*)(up + k0 + sK);
            const float4 u1 = *(const float4*)(up + k0 + sK + 4);
            Asm[sK + 0][sRow] = (h0.x + t0.x) * u0.x;
            Asm[sK + 1][sRow] = (h0.y + t0.y) * u0.y;
            Asm[sK + 2][sRow] = (h0.z + t0.z) * u0.z;
            Asm[sK + 3][sRow] = (h0.w + t0.w) * u0.w;
            Asm[sK + 4][sRow] = (h1.x + t1.x) * u1.x;
            Asm[sK + 5][sRow] = (h1.y + t1.y) * u1.y;
            Asm[sK + 6][sRow] = (h1.z + t1.z) * u1.z;
            Asm[sK + 7][sRow] = (h1.w + t1.w) * u1.w;
        }
        {
            const float* src = wp + (size_t)k0 * NUM_REL_CLS;
            #pragma unroll
            for (int t = 0; t < 7; t++) {
                const int idx = tid + t * 256;
                if (idx < FBK * NUM_REL_CLS) {
                    Wsm[idx / NUM_REL_CLS][idx % NUM_REL_CLS] = src[idx];
                }
            }
        }
        __syncthreads();

        #pragma unroll 8
        for (int kk = 0; kk < FBK; kk++) {
            const float4 a = *(const float4*)&Asm[kk][tr4];
            const float4 b = *(const float4*)&Wsm[kk][tc4];
            acc[0][0] = fmaf(a.x, b.x, acc[0][0]);
            acc[0][1] = fmaf(a.x, b.y, acc[0][1]);
            acc[0][2] = fmaf(a.x, b.z, acc[0][2]);
            acc[0][3] = fmaf(a.x, b.w, acc[0][3]);
            acc[1][0] = fmaf(a.y, b.x, acc[1][0]);
            acc[1][1] = fmaf(a.y, b.y, acc[1][1]);
            acc[1][2] = fmaf(a.y, b.z, acc[1][2]);
            acc[1][3] = fmaf(a.y, b.w, acc[1][3]);
            acc[2][0] = fmaf(a.z, b.x, acc[2][0]);
            acc[2][1] = fmaf(a.z, b.y, acc[2][1]);
            acc[2][2] = fmaf(a.z, b.z, acc[2][2]);
            acc[2][3] = fmaf(a.z, b.w, acc[2][3]);
            acc[3][0] = fmaf(a.w, b.x, acc[3][0]);
            acc[3][1] = fmaf(a.w, b.y, acc[3][1]);
            acc[3][2] = fmaf(a.w, b.z, acc[3][2]);
            acc[3][3] = fmaf(a.w, b.w, acc[3][3]);
        }
    }

    float* pbase = part + ((size_t)sp * N_REL + rBase) * NPAD;
    #pragma unroll
    for (int m = 0; m < 4; m++) {
        float4 v;
        v.x = acc[m][0]; v.y = acc[m][1]; v.z = acc[m][2]; v.w = acc[m][3];
        *(float4*)&pbase[(size_t)(tr4 + m) * NPAD + tc4] = v;
    }
}

__global__ __launch_bounds__(256) void combine_rel(
    const float* __restrict__ part,
    const float* __restrict__ br,
    const float* __restrict__ freq,
    const int* __restrict__ pair_idx,
    const int* __restrict__ obj_preds,
    float* __restrict__ out)
{
    const int r = blockIdx.x * 4 + (threadIdx.x >> 6);
    const int c = threadIdx.x & 63;
    if (c >= NUM_REL_CLS) return;

    const int bi = obj_preds[pair_idx[2 * r]] * NUM_OBJ_CLS
                 + obj_preds[pair_idx[2 * r + 1]];
    float s = 0.0f;
    #pragma unroll
    for (int sp = 0; sp < SPLITK; sp++)
        s += part[((size_t)sp * N_REL + r) * NPAD + c];
    out[(size_t)r * NUM_REL_CLS + c] = s + br[c] + freq[(size_t)bi * NUM_REL_CLS + c];
}

// =====================================================================
// Launch
// =====================================================================
extern "C" void kernel_launch(void* const* d_in, const int* in_sizes, int n_in,
                              void* d_out, int out_size)
{
    const float* edge_ctx   = (const float*)d_in[0];
    const float* U          = (const float*)d_in[1];
    const float* W_post_emb = (const float*)d_in[2];
    const float* b_post_emb = (const float*)d_in[3];
    const float* W_post_cat = (const float*)d_in[4];
    const float* b_post_cat = (const float*)d_in[5];
    const float* W_rel      = (const float*)d_in[6];
    const float* b_rel      = (const float*)d_in[7];
    const float* freq       = (const float*)d_in[8];
    const int*   pair_idx   = (const int*)d_in[9];
    const int*   obj_preds  = (const int*)d_in[10];
    float* out = (float*)d_out;

    float *ep, *hc, *tc, *part;
    __nv_bfloat16 *ahi, *alo, *bhi, *blo;
    cudaGetSymbolAddress((void**)&ep, g_edge_rep);
    cudaGetSymbolAddress((void**)&hc, g_head_cat);
    cudaGetSymbolAddress((void**)&tc, g_tail_cat);
    cudaGetSymbolAddress((void**)&part, g_part);
    cudaGetSymbolAddress((void**)&ahi, g_A_hi);
    cudaGetSymbolAddress((void**)&alo, g_A_lo);
    cudaGetSymbolAddress((void**)&bhi, g_Bt_hi);
    cudaGetSymbolAddress((void**)&blo, g_Bt_lo);

    // B transpose+split (independent of K1)
    transpose_split_B<<<dim3(POOL / 32, (2 * HID) / 32), 256>>>(W_post_cat, bhi, blo);

    // K1: edge_rep = edge_ctx @ W_post_emb + b_post_emb
    k1_gemm<<<dim3((2 * HID) / GBN, N_OBJ / GBM), 256>>>(
        edge_ctx, W_post_emb, b_post_emb, ep);

    // split edge_rep into bf16 hi/lo
    split_A<<<(N_OBJ * 2 * HID + 255) / 256, 256>>>(ep, ahi, alo, N_OBJ * 2 * HID);

    // K2: head_cat / tail_cat via HMMA
    k2_hmma<<<dim3(POOL / 64, N_OBJ / 128, 2), 256>>>(
        ahi, alo, bhi, blo, b_post_cat, hc, tc);

    // K3: split-K fused GEMM -> partials
    fused_rel3<<<dim3(N_REL / FRM, SPLITK), 256>>>(
        U, hc, tc, W_rel, pair_idx, part);

    // K4: combine
    combine_rel<<<N_REL / 4, 256>>>(part, b_rel, freq, pair_idx, obj_preds, out);
}

// round 7
// speedup vs baseline: 3.4159x; 1.4066x over previous
#include <cuda_runtime.h>
#include <cuda_bf16.h>
#include <cstdint>

#define HID 512
#define POOL 4096
#define N_OBJ 1280
#define N_REL 16384
#define NUM_OBJ_CLS 151
#define NUM_REL_CLS 51
#define NPAD 64

// K3 tiling
#define R3_M 64
#define R3_BK 64
#define R3_SPLITK 2
#define R3_KS (POOL / R3_SPLITK)   // 2048

// -------- scratch (device globals; no allocation allowed) --------
__device__ float g_edge_rep[N_OBJ * 2 * HID];
__device__ float g_head_cat[N_OBJ * POOL];
__device__ float g_tail_cat[N_OBJ * POOL];
__device__ float g_part[R3_SPLITK * N_REL * NPAD];       // 8.4MB
__device__ __nv_bfloat16 g_A_hi[N_OBJ * 2 * HID];
__device__ __nv_bfloat16 g_A_lo[N_OBJ * 2 * HID];
__device__ __nv_bfloat16 g_Bt_hi[POOL * 2 * HID];        // W_post_cat^T
__device__ __nv_bfloat16 g_Bt_lo[POOL * 2 * HID];
__device__ __nv_bfloat16 g_Wt_hi[NPAD * POOL];           // W_rel^T, rows>=51 zero
__device__ __nv_bfloat16 g_Wt_lo[NPAD * POOL];

// =====================================================================
// helpers
// =====================================================================
__device__ __forceinline__ uint32_t smem_u32(const void* p) {
    uint32_t a;
    asm("{ .reg .u64 t; cvta.to.shared.u64 t, %1; cvt.u32.u64 %0, t; }"
        : "=r"(a) : "l"(p));
    return a;
}
#define SWZ128(off) ((off) ^ (((off) >> 3) & 0x70))

__device__ __forceinline__ void ldsm_x4(uint32_t* r, uint32_t addr) {
    asm volatile("ldmatrix.sync.aligned.m8n8.x4.shared.b16 {%0,%1,%2,%3}, [%4];"
                 : "=r"(r[0]), "=r"(r[1]), "=r"(r[2]), "=r"(r[3]) : "r"(addr));
}

__device__ __forceinline__ void mma_bf16(float* d, const uint32_t* a, const uint32_t* b) {
    asm volatile(
        "mma.sync.aligned.m16n8k16.row.col.f32.bf16.bf16.f32 "
        "{%0,%1,%2,%3}, {%4,%5,%6,%7}, {%8,%9}, {%0,%1,%2,%3};"
        : "+f"(d[0]), "+f"(d[1]), "+f"(d[2]), "+f"(d[3])
        : "r"(a[0]), "r"(a[1]), "r"(a[2]), "r"(a[3]), "r"(b[0]), "r"(b[1]));
}

__device__ __forceinline__ uint32_t pack_hi(float a, float b) {
    __nv_bfloat162 h;
    h.x = __float2bfloat16(a);
    h.y = __float2bfloat16(b);
    return *(uint32_t*)&h;
}
__device__ __forceinline__ uint32_t pack_lo(float a, float b, uint32_t hw) {
    __nv_bfloat162 h = *(__nv_bfloat162*)&hw;
    __nv_bfloat162 l;
    l.x = __float2bfloat16(a - __bfloat162float(h.x));
    l.y = __float2bfloat16(b - __bfloat162float(h.y));
    return *(uint32_t*)&l;
}

// =====================================================================
// Pre-split kernels
// =====================================================================
__global__ __launch_bounds__(256) void split_A(
    const float* __restrict__ src, __nv_bfloat16* __restrict__ hi,
    __nv_bfloat16* __restrict__ lo, int n)
{
    int i = blockIdx.x * 256 + threadIdx.x;
    if (i >= n) return;
    float x = src[i];
    __nv_bfloat16 h = __float2bfloat16(x);
    hi[i] = h;
    lo[i] = __float2bfloat16(x - __bfloat162float(h));
}

__global__ __launch_bounds__(256) void transpose_split_B(
    const float* __restrict__ W,
    __nv_bfloat16* __restrict__ bhi, __nv_bfloat16* __restrict__ blo)
{
    __shared__ float t[32][33];
    const int kb = blockIdx.y * 32;
    const int nb = blockIdx.x * 32;
    const int tx = threadIdx.x & 31;
    const int ty = threadIdx.x >> 5;
    #pragma unroll
    for (int s = 0; s < 4; s++)
        t[ty + s * 8][tx] = W[(size_t)(kb + ty + s * 8) * POOL + nb + tx];
    __syncthreads();
    #pragma unroll
    for (int s = 0; s < 4; s++) {
        const int n = nb + ty + s * 8;
        const float x = t[tx][ty + s * 8];
        __nv_bfloat16 h = __float2bfloat16(x);
        const size_t o = (size_t)n * (2 * HID) + kb + tx;
        bhi[o] = h;
        blo[o] = __float2bfloat16(x - __bfloat162float(h));
    }
}

// W_rel [4096][51] -> Wt [64][4096] bf16 hi/lo (rows >= 51 zero)
__global__ __launch_bounds__(256) void transpose_split_Wrel(
    const float* __restrict__ Wr,
    __nv_bfloat16* __restrict__ whi, __nv_bfloat16* __restrict__ wlo)
{
    __shared__ float t[32][33];
    const int kb = blockIdx.y * 32;
    const int nb = blockIdx.x * 32;
    const int tx = threadIdx.x & 31;
    const int ty = threadIdx.x >> 5;
    #pragma unroll
    for (int s = 0; s < 4; s++) {
        const int k = kb + ty + s * 8;
        const int n = nb + tx;
        t[ty + s * 8][tx] = (n < NUM_REL_CLS) ? Wr[(size_t)k * NUM_REL_CLS + n] : 0.0f;
    }
    __syncthreads();
    #pragma unroll
    for (int s = 0; s < 4; s++) {
        const int n = nb + ty + s * 8;
        const float x = t[tx][ty + s * 8];
        __nv_bfloat16 h = __float2bfloat16(x);
        const size_t o = (size_t)n * POOL + kb + tx;
        whi[o] = h;
        wlo[o] = __float2bfloat16(x - __bfloat162float(h));
    }
}

// =====================================================================
// K2 via HMMA (unchanged from R6, passing)
// =====================================================================
#define K2_BK 64
#define S_AHI 0
#define S_ALO 16384
#define S_BHI 32768
#define S_BLO 40960

__global__ __launch_bounds__(256) void k2_hmma(
    const __nv_bfloat16* __restrict__ Ahi, const __nv_bfloat16* __restrict__ Alo,
    const __nv_bfloat16* __restrict__ Bhi, const __nv_bfloat16* __restrict__ Blo,
    const float* __restrict__ bpc,
    float* __restrict__ hc, float* __restrict__ tcat)
{
    __shared__ char smem[49152];
    const uint32_t sb = smem_u32(smem);
    const int tid = threadIdx.x;
    const int wid = tid >> 5;
    const int lane = tid & 31;
    const int bx = blockIdx.x;
    const int by = blockIdx.y;
    const int z = blockIdx.z;
    const int koff = z * HID;

    const int m0 = (wid >> 1) * 32;
    const int n0 = (wid & 1) * 32;

    float acc[2][4][4];
    #pragma unroll
    for (int mf = 0; mf < 2; mf++)
        #pragma unroll
        for (int nf = 0; nf < 4; nf++)
            #pragma unroll
            for (int e = 0; e < 4; e++) acc[mf][nf][e] = 0.0f;

    const int aRowOff = (m0 + (lane & 15)) * 128 + ((lane & 16) ? 16 : 0);
    const int bRowOff = (n0 + (lane & 7) + ((lane & 16) ? 8 : 0)) * 128 + ((lane & 8) ? 16 : 0);

    for (int ch = 0; ch < HID / K2_BK; ch++) {
        const int k0 = koff + ch * K2_BK;
        __syncthreads();

        #pragma unroll
        for (int g = tid; g < 1024; g += 256) {
            const int row = g >> 3, grp = g & 7;
            const size_t src = (size_t)(by * 128 + row) * (2 * HID) + k0 + grp * 8;
            const uint32_t dst = SWZ128((uint32_t)(row * 128 + grp * 16));
            *(uint4*)(smem + S_AHI + dst) = *(const uint4*)(Ahi + src);
            *(uint4*)(smem + S_ALO + dst) = *(const uint4*)(Alo + src);
        }
        #pragma unroll
        for (int g = tid; g < 512; g += 256) {
            const int row = g >> 3, grp = g & 7;
            const size_t src = (size_t)(bx * 64 + row) * (2 * HID) + k0 + grp * 8;
            const uint32_t dst = SWZ128((uint32_t)(row * 128 + grp * 16));
            *(uint4*)(smem + S_BHI + dst) = *(const uint4*)(Bhi + src);
            *(uint4*)(smem + S_BLO + dst) = *(const uint4*)(Blo + src);
        }
        __syncthreads();

        #pragma unroll
        for (int kk = 0; kk < K2_BK; kk += 16) {
            uint32_t ahi[2][4], alo[2][4], bh[2][4], bl[2][4];
            #pragma unroll
            for (int mf = 0; mf < 2; mf++) {
                const uint32_t off = SWZ128((uint32_t)(aRowOff + mf * 16 * 128 + kk * 2));
                ldsm_x4(ahi[mf], sb + S_AHI + off);
                ldsm_x4(alo[mf], sb + S_ALO + off);
            }
            #pragma unroll
            for (int nf2 = 0; nf2 < 2; nf2++) {
                const uint32_t off = SWZ128((uint32_t)(bRowOff + nf2 * 16 * 128 + kk * 2));
                ldsm_x4(bh[nf2], sb + S_BHI + off);
                ldsm_x4(bl[nf2], sb + S_BLO + off);
            }
            #pragma unroll
            for (int mf = 0; mf < 2; mf++) {
                #pragma unroll
                for (int nf = 0; nf < 4; nf++) {
                    const uint32_t* bhp = &bh[nf >> 1][(nf & 1) * 2];
                    const uint32_t* blp = &bl[nf >> 1][(nf & 1) * 2];
                    mma_bf16(acc[mf][nf], ahi[mf], bhp);
                    mma_bf16(acc[mf][nf], ahi[mf], blp);
                    mma_bf16(acc[mf][nf], alo[mf], bhp);
                }
            }
        }
    }

    const int gm = by * 128 + m0 + (lane >> 2);
    const int gn = bx * 64 + n0 + (lane & 3) * 2;
    float* Cb = (z == 0 ? hc : tcat);
    #pragma unroll
    for (int mf = 0; mf < 2; mf++) {
        #pragma unroll
        for (int nf = 0; nf < 4; nf++) {
            const int col = gn + nf * 8;
            float b0 = 0.0f, b1 = 0.0f;
            if (z == 0) { b0 = bpc[col]; b1 = bpc[col + 1]; }
            const int r0 = gm + mf * 16;
            float2 v0, v1;
            v0.x = acc[mf][nf][0] + b0;
            v0.y = acc[mf][nf][1] + b1;
            v1.x = acc[mf][nf][2] + b0;
            v1.y = acc[mf][nf][3] + b1;
            *(float2*)&Cb[(size_t)r0 * POOL + col] = v0;
            *(float2*)&Cb[(size_t)(r0 + 8) * POOL + col] = v1;
        }
    }
}

// =====================================================================
// K3 via HMMA: part[sp] += A @ Wt^T where A[r,k] = (HC[i]+TC[j])*U[r]
// built on the fly (fp32 -> bf16 hi/lo) into SW128 smem.
// Tile M=64 x N=64, BK=64, K per split = 2048. 8 warps (2m x 4n).
// smem: A_hi 8K | A_lo 8K | B_hi 8K | B_lo 8K = 32KB
// =====================================================================
#define R3_AHI 0
#define R3_ALO 8192
#define R3_BHI 16384
#define R3_BLO 24576

__global__ __launch_bounds__(256) void k3_hmma(
    const float* __restrict__ U,
    const float* __restrict__ HC,
    const float* __restrict__ TC,
    const __nv_bfloat16* __restrict__ Whi,  // [64][4096]
    const __nv_bfloat16* __restrict__ Wlo,
    const int* __restrict__ pair_idx,
    float* __restrict__ part)               // [R3_SPLITK][N_REL][NPAD]
{
    __shared__ char smem[32768];
    const uint32_t sb = smem_u32(smem);
    const int tid = threadIdx.x;
    const int wid = tid >> 5;
    const int lane = tid & 31;
    const int rBase = blockIdx.x * R3_M;
    const int sp = blockIdx.y;
    const int kb = sp * R3_KS;

    const int m0 = (wid >> 2) * 32;     // 0 or 32
    const int n0 = (wid & 3) * 16;      // 0,16,32,48

    // staging: row = tid>>2, 16 consecutive k at (tid&3)*16
    const int sRow = tid >> 2;
    const int sK = (tid & 3) * 16;
    const int grow = rBase + sRow;
    const int si = pair_idx[2 * grow];
    const int sj = pair_idx[2 * grow + 1];
    const float* hp = HC + (size_t)si * POOL + kb + sK;
    const float* tp = TC + (size_t)sj * POOL + kb + sK;
    const float* up = U  + (size_t)grow * POOL + kb + sK;
    const int sgrp = (tid & 3) * 2;     // 16B-group index base within row

    float acc[2][2][4];
    #pragma unroll
    for (int mf = 0; mf < 2; mf++)
        #pragma unroll
        for (int nf = 0; nf < 2; nf++)
            #pragma unroll
            for (int e = 0; e < 4; e++) acc[mf][nf][e] = 0.0f;

    const int aRowOff = (m0 + (lane & 15)) * 128 + ((lane & 16) ? 16 : 0);
    const int bRowOff = (n0 + (lane & 7) + ((lane & 16) ? 8 : 0)) * 128 + ((lane & 8) ? 16 : 0);

    for (int ch = 0; ch < R3_KS / R3_BK; ch++) {
        const int k0 = ch * R3_BK;
        __syncthreads();

        // ---- stage A: compute m = (hc+tc)*u for 16 k, split hi/lo, pack ----
        {
            float mv[16];
            #pragma unroll
            for (int s = 0; s < 4; s++) {
                const float4 h = *(const float4*)(hp + k0 + s * 4);
                const float4 t = *(const float4*)(tp + k0 + s * 4);
                const float4 u = *(const float4*)(up + k0 + s * 4);
                mv[s * 4 + 0] = (h.x + t.x) * u.x;
                mv[s * 4 + 1] = (h.y + t.y) * u.y;
                mv[s * 4 + 2] = (h.z + t.z) * u.z;
                mv[s * 4 + 3] = (h.w + t.w) * u.w;
            }
            #pragma unroll
            for (int g2 = 0; g2 < 2; g2++) {
                uint4 hw, lw;
                uint32_t* hp4 = (uint32_t*)&hw;
                uint32_t* lp4 = (uint32_t*)&lw;
                #pragma unroll
                for (int p = 0; p < 4; p++) {
                    const float a = mv[g2 * 8 + p * 2];
                    const float b = mv[g2 * 8 + p * 2 + 1];
                    hp4[p] = pack_hi(a, b);
                    lp4[p] = pack_lo(a, b, hp4[p]);
                }
                const uint32_t dst = SWZ128((uint32_t)(sRow * 128 + (sgrp + g2) * 16));
                *(uint4*)(smem + R3_AHI + dst) = hw;
                *(uint4*)(smem + R3_ALO + dst) = lw;
            }
        }

        // ---- stage B: Wt tile 64 rows(n) x 64 k bf16 hi/lo ----
        #pragma unroll
        for (int g = tid; g < 512; g += 256) {
            const int row = g >> 3, grp = g & 7;
            const size_t src = (size_t)row * POOL + kb + k0 + grp * 8;
            const uint32_t dst = SWZ128((uint32_t)(row * 128 + grp * 16));
            *(uint4*)(smem + R3_BHI + dst) = *(const uint4*)(Whi + src);
            *(uint4*)(smem + R3_BLO + dst) = *(const uint4*)(Wlo + src);
        }
        __syncthreads();

        #pragma unroll
        for (int kk = 0; kk < R3_BK; kk += 16) {
            uint32_t ahi[2][4], alo[2][4], bh[4], bl[4];
            #pragma unroll
            for (int mf = 0; mf < 2; mf++) {
                const uint32_t off = SWZ128((uint32_t)(aRowOff + mf * 16 * 128 + kk * 2));
                ldsm_x4(ahi[mf], sb + R3_AHI + off);
                ldsm_x4(alo[mf], sb + R3_ALO + off);
            }
            {
                const uint32_t off = SWZ128((uint32_t)(bRowOff + kk * 2));
                ldsm_x4(bh, sb + R3_BHI + off);
                ldsm_x4(bl, sb + R3_BLO + off);
            }
            #pragma unroll
            for (int mf = 0; mf < 2; mf++) {
                #pragma unroll
                for (int nf = 0; nf < 2; nf++) {
                    const uint32_t* bhp = &bh[nf * 2];
                    const uint32_t* blp = &bl[nf * 2];
                    mma_bf16(acc[mf][nf], ahi[mf], bhp);
                    mma_bf16(acc[mf][nf], ahi[mf], blp);
                    mma_bf16(acc[mf][nf], alo[mf], bhp);
                }
            }
        }
    }

    // epilogue -> partials
    const int gm = rBase + m0 + (lane >> 2);
    const int gn = n0 + (lane & 3) * 2;
    float* pb = part + (size_t)sp * N_REL * NPAD;
    #pragma unroll
    for (int mf = 0; mf < 2; mf++) {
        #pragma unroll
        for (int nf = 0; nf < 2; nf++) {
            const int col = gn + nf * 8;
            const int r0 = gm + mf * 16;
            float2 v0, v1;
            v0.x = acc[mf][nf][0];
            v0.y = acc[mf][nf][1];
            v1.x = acc[mf][nf][2];
            v1.y = acc[mf][nf][3];
            *(float2*)&pb[(size_t)r0 * NPAD + col] = v0;
            *(float2*)&pb[(size_t)(r0 + 8) * NPAD + col] = v1;
        }
    }
}

// =====================================================================
// combine: out[r,c] = sum_sp part[sp,r,c] + b_rel[c] + freq[bidx_r,c]
// =====================================================================
__global__ __launch_bounds__(256) void combine_rel(
    const float* __restrict__ part,
    const float* __restrict__ br,
    const float* __restrict__ freq,
    const int* __restrict__ pair_idx,
    const int* __restrict__ obj_preds,
    float* __restrict__ out)
{
    const int r = blockIdx.x * 4 + (threadIdx.x >> 6);
    const int c = threadIdx.x & 63;
    if (c >= NUM_REL_CLS) return;

    const int bi = obj_preds[pair_idx[2 * r]] * NUM_OBJ_CLS
                 + obj_preds[pair_idx[2 * r + 1]];
    float s = 0.0f;
    #pragma unroll
    for (int sp = 0; sp < R3_SPLITK; sp++)
        s += part[((size_t)sp * N_REL + r) * NPAD + c];
    out[(size_t)r * NUM_REL_CLS + c] = s + br[c] + freq[(size_t)bi * NUM_REL_CLS + c];
}

// =====================================================================
// fp32 GEMM (K1): BM=128, BN=64, BK=8, 256 thr, 8x4 microtile.
// =====================================================================
#define GBM 128
#define GBN 64
#define GBK 8
#define ASTR_G 132

__global__ __launch_bounds__(256, 2) void k1_gemm(
    const float* __restrict__ A, const float* __restrict__ B,
    const float* __restrict__ bias, float* __restrict__ C)
{
    __shared__ float As[2][GBK][ASTR_G];
    __shared__ float Bs[2][GBK][GBN];

    const int tid = threadIdx.x;
    const int rowBase = blockIdx.y * GBM;
    const int colBase = blockIdx.x * GBN;
    const int lda = HID, ldb = 2 * HID, ldc = 2 * HID, K = HID;

    const int aRow = tid >> 1;
    const int aCol = (tid & 1) * 4;
    const int bRow = tid >> 5;
    const int bCol = (tid & 31) * 2;

    const float* Aptr = A + (size_t)(rowBase + aRow) * lda + aCol;
    const float* Bptr = B + (size_t)bRow * ldb + colBase + bCol;

    const int tr8 = (tid >> 4) * 8;
    const int tc4 = (tid & 15) * 4;

    float acc[8][4];
    #pragma unroll
    for (int m = 0; m < 8; m++)
        #pragma unroll
        for (int n = 0; n < 4; n++) acc[m][n] = 0.0f;

    float4 a4 = *(const float4*)(Aptr);
    float2 b2 = *(const float2*)(Bptr);
    As[0][aCol + 0][aRow] = a4.x;
    As[0][aCol + 1][aRow] = a4.y;
    As[0][aCol + 2][aRow] = a4.z;
    As[0][aCol + 3][aRow] = a4.w;
    *(float2*)&Bs[0][bRow][bCol] = b2;
    __syncthreads();

    int buf = 0;
    for (int k0 = 0; k0 < K; k0 += GBK) {
        const bool has_next = (k0 + GBK) < K;
        if (has_next) {
            a4 = *(const float4*)(Aptr + k0 + GBK);
            b2 = *(const float2*)(Bptr + (size_t)(k0 + GBK) * ldb);
        }
        #pragma unroll
        for (int kk = 0; kk < GBK; kk++) {
            float4 ra0 = *(const float4*)&As[buf][kk][tr8];
            float4 ra1 = *(const float4*)&As[buf][kk][tr8 + 4];
            float4 rb  = *(const float4*)&Bs[buf][kk][tc4];
            float ra[8] = {ra0.x, ra0.y, ra0.z, ra0.w, ra1.x, ra1.y, ra1.z, ra1.w};
            float rbv[4] = {rb.x, rb.y, rb.z, rb.w};
            #pragma unroll
            for (int m = 0; m < 8; m++)
                #pragma unroll
                for (int n = 0; n < 4; n++)
                    acc[m][n] = fmaf(ra[m], rbv[n], acc[m][n]);
        }
        if (has_next) {
            const int nb = buf ^ 1;
            As[nb][aCol + 0][aRow] = a4.x;
            As[nb][aCol + 1][aRow] = a4.y;
            As[nb][aCol + 2][aRow] = a4.z;
            As[nb][aCol + 3][aRow] = a4.w;
            *(float2*)&Bs[nb][bRow][bCol] = b2;
            __syncthreads();
            buf = nb;
        }
    }

    #pragma unroll
    for (int m = 0; m < 8; m++) {
        const int row = rowBase + tr8 + m;
        const int col = colBase + tc4;
        float4 v;
        v.x = acc[m][0] + bias[col + 0];
        v.y = acc[m][1] + bias[col + 1];
        v.z = acc[m][2] + bias[col + 2];
        v.w = acc[m][3] + bias[col + 3];
        *(float4*)&C[(size_t)row * ldc + col] = v;
    }
}

// =====================================================================
// Launch
// =====================================================================
extern "C" void kernel_launch(void* const* d_in, const int* in_sizes, int n_in,
                              void* d_out, int out_size)
{
    const float* edge_ctx   = (const float*)d_in[0];
    const float* U          = (const float*)d_in[1];
    const float* W_post_emb = (const float*)d_in[2];
    const float* b_post_emb = (const float*)d_in[3];
    const float* W_post_cat = (const float*)d_in[4];
    const float* b_post_cat = (const float*)d_in[5];
    const float* W_rel      = (const float*)d_in[6];
    const float* b_rel      = (const float*)d_in[7];
    const float* freq       = (const float*)d_in[8];
    const int*   pair_idx   = (const int*)d_in[9];
    const int*   obj_preds  = (const int*)d_in[10];
    float* out = (float*)d_out;

    float *ep, *hc, *tc, *part;
    __nv_bfloat16 *ahi, *alo, *bhi, *blo, *whi, *wlo;
    cudaGetSymbolAddress((void**)&ep, g_edge_rep);
    cudaGetSymbolAddress((void**)&hc, g_head_cat);
    cudaGetSymbolAddress((void**)&tc, g_tail_cat);
    cudaGetSymbolAddress((void**)&part, g_part);
    cudaGetSymbolAddress((void**)&ahi, g_A_hi);
    cudaGetSymbolAddress((void**)&alo, g_A_lo);
    cudaGetSymbolAddress((void**)&bhi, g_Bt_hi);
    cudaGetSymbolAddress((void**)&blo, g_Bt_lo);
    cudaGetSymbolAddress((void**)&whi, g_Wt_hi);
    cudaGetSymbolAddress((void**)&wlo, g_Wt_lo);

    // weight preprocessing (independent of K1)
    transpose_split_Wrel<<<dim3(NPAD / 32, POOL / 32), 256>>>(W_rel, whi, wlo);
    transpose_split_B<<<dim3(POOL / 32, (2 * HID) / 32), 256>>>(W_post_cat, bhi, blo);

    // K1: edge_rep = edge_ctx @ W_post_emb + b_post_emb
    k1_gemm<<<dim3((2 * HID) / GBN, N_OBJ / GBM), 256>>>(
        edge_ctx, W_post_emb, b_post_emb, ep);

    // split edge_rep into bf16 hi/lo
    split_A<<<(N_OBJ * 2 * HID + 255) / 256, 256>>>(ep, ahi, alo, N_OBJ * 2 * HID);

    // K2: head_cat / tail_cat via HMMA
    k2_hmma<<<dim3(POOL / 64, N_OBJ / 128, 2), 256>>>(
        ahi, alo, bhi, blo, b_post_cat, hc, tc);

    // K3: fused gather+elementwise GEMM via HMMA -> split-K partials
    k3_hmma<<<dim3(N_REL / R3_M, R3_SPLITK), 256>>>(
        U, hc, tc, whi, wlo, pair_idx, part);

    // K4: combine
    combine_rel<<<N_REL / 4, 256>>>(part, b_rel, freq, pair_idx, obj_preds, out);
}

// round 8
// speedup vs baseline: 3.9509x; 1.1566x over previous
#include <cuda_runtime.h>
#include <cuda_bf16.h>
#include <cstdint>

#define HID 512
#define POOL 4096
#define N_OBJ 1280
#define N_REL 16384
#define NUM_OBJ_CLS 151
#define NUM_REL_CLS 51
#define NPAD 64

// K3 tiling
#define R3_M 64
#define R3_BK 64
#define R3_SPLITK 2
#define R3_KS (POOL / R3_SPLITK)   // 2048
#define R3_NCH (R3_KS / R3_BK)     // 32
#define R3_STAGE 32768
#define R3_AHI 0
#define R3_ALO 8192
#define R3_BHI 16384
#define R3_BLO 24576

// K2 tiling
#define K2_BK 64
#define K2_NCH (HID / K2_BK)       // 8
#define K2_STAGE 49152
#define S_AHI 0
#define S_ALO 16384
#define S_BHI 32768
#define S_BLO 40960

// -------- scratch (device globals; no allocation allowed) --------
__device__ float g_head_cat[N_OBJ * POOL];
__device__ float g_tail_cat[N_OBJ * POOL];
__device__ float g_part[R3_SPLITK * N_REL * NPAD];
__device__ __nv_bfloat16 g_A_hi[N_OBJ * 2 * HID];
__device__ __nv_bfloat16 g_A_lo[N_OBJ * 2 * HID];
__device__ __nv_bfloat16 g_Bt_hi[POOL * 2 * HID];        // W_post_cat^T
__device__ __nv_bfloat16 g_Bt_lo[POOL * 2 * HID];
__device__ __nv_bfloat16 g_Wt_hi[NPAD * POOL];           // W_rel^T, rows>=51 zero
__device__ __nv_bfloat16 g_Wt_lo[NPAD * POOL];

// =====================================================================
// helpers
// =====================================================================
__device__ __forceinline__ uint32_t smem_u32(const void* p) {
    uint32_t a;
    asm("{ .reg .u64 t; cvta.to.shared.u64 t, %1; cvt.u32.u64 %0, t; }"
        : "=r"(a) : "l"(p));
    return a;
}
#define SWZ128(off) ((off) ^ (((off) >> 3) & 0x70))

__device__ __forceinline__ void cp16(uint32_t s, const void* g) {
    asm volatile("cp.async.cg.shared.global [%0], [%1], 16;" :: "r"(s), "l"(g));
}
#define CP_COMMIT() asm volatile("cp.async.commit_group;" ::: "memory")
#define CP_WAIT0()  asm volatile("cp.async.wait_group 0;" ::: "memory")
#define CP_WAIT1()  asm volatile("cp.async.wait_group 1;" ::: "memory")

__device__ __forceinline__ void ldsm_x4(uint32_t* r, uint32_t addr) {
    asm volatile("ldmatrix.sync.aligned.m8n8.x4.shared.b16 {%0,%1,%2,%3}, [%4];"
                 : "=r"(r[0]), "=r"(r[1]), "=r"(r[2]), "=r"(r[3]) : "r"(addr));
}

__device__ __forceinline__ void mma_bf16(float* d, const uint32_t* a, const uint32_t* b) {
    asm volatile(
        "mma.sync.aligned.m16n8k16.row.col.f32.bf16.bf16.f32 "
        "{%0,%1,%2,%3}, {%4,%5,%6,%7}, {%8,%9}, {%0,%1,%2,%3};"
        : "+f"(d[0]), "+f"(d[1]), "+f"(d[2]), "+f"(d[3])
        : "r"(a[0]), "r"(a[1]), "r"(a[2]), "r"(a[3]), "r"(b[0]), "r"(b[1]));
}

__device__ __forceinline__ uint32_t pack_hi(float a, float b) {
    __nv_bfloat162 h;
    h.x = __float2bfloat16(a);
    h.y = __float2bfloat16(b);
    return *(uint32_t*)&h;
}
__device__ __forceinline__ uint32_t pack_lo(float a, float b, uint32_t hw) {
    __nv_bfloat162 h = *(__nv_bfloat162*)&hw;
    __nv_bfloat162 l;
    l.x = __float2bfloat16(a - __bfloat162float(h.x));
    l.y = __float2bfloat16(b - __bfloat162float(h.y));
    return *(uint32_t*)&l;
}

// =====================================================================
// weight preprocessing
// =====================================================================
__global__ __launch_bounds__(256) void transpose_split_B(
    const float* __restrict__ W,
    __nv_bfloat16* __restrict__ bhi, __nv_bfloat16* __restrict__ blo)
{
    __shared__ float t[32][33];
    const int kb = blockIdx.y * 32;
    const int nb = blockIdx.x * 32;
    const int tx = threadIdx.x & 31;
    const int ty = threadIdx.x >> 5;
    #pragma unroll
    for (int s = 0; s < 4; s++)
        t[ty + s * 8][tx] = W[(size_t)(kb + ty + s * 8) * POOL + nb + tx];
    __syncthreads();
    #pragma unroll
    for (int s = 0; s < 4; s++) {
        const int n = nb + ty + s * 8;
        const float x = t[tx][ty + s * 8];
        __nv_bfloat16 h = __float2bfloat16(x);
        const size_t o = (size_t)n * (2 * HID) + kb + tx;
        bhi[o] = h;
        blo[o] = __float2bfloat16(x - __bfloat162float(h));
    }
}

__global__ __launch_bounds__(256) void transpose_split_Wrel(
    const float* __restrict__ Wr,
    __nv_bfloat16* __restrict__ whi, __nv_bfloat16* __restrict__ wlo)
{
    __shared__ float t[32][33];
    const int kb = blockIdx.y * 32;
    const int nb = blockIdx.x * 32;
    const int tx = threadIdx.x & 31;
    const int ty = threadIdx.x >> 5;
    #pragma unroll
    for (int s = 0; s < 4; s++) {
        const int k = kb + ty + s * 8;
        const int n = nb + tx;
        t[ty + s * 8][tx] = (n < NUM_REL_CLS) ? Wr[(size_t)k * NUM_REL_CLS + n] : 0.0f;
    }
    __syncthreads();
    #pragma unroll
    for (int s = 0; s < 4; s++) {
        const int n = nb + ty + s * 8;
        const float x = t[tx][ty + s * 8];
        __nv_bfloat16 h = __float2bfloat16(x);
        const size_t o = (size_t)n * POOL + kb + tx;
        whi[o] = h;
        wlo[o] = __float2bfloat16(x - __bfloat162float(h));
    }
}

// =====================================================================
// K1: edge_rep GEMM, epilogue writes bf16 hi/lo directly (fused split).
// =====================================================================
#define GBM 128
#define GBN 64
#define GBK 8
#define ASTR_G 132

__global__ __launch_bounds__(256, 2) void k1_gemm(
    const float* __restrict__ A, const float* __restrict__ B,
    const float* __restrict__ bias,
    __nv_bfloat16* __restrict__ Ohi, __nv_bfloat16* __restrict__ Olo)
{
    __shared__ float As[2][GBK][ASTR_G];
    __shared__ float Bs[2][GBK][GBN];

    const int tid = threadIdx.x;
    const int rowBase = blockIdx.y * GBM;
    const int colBase = blockIdx.x * GBN;
    const int lda = HID, ldb = 2 * HID, K = HID;

    const int aRow = tid >> 1;
    const int aCol = (tid & 1) * 4;
    const int bRow = tid >> 5;
    const int bCol = (tid & 31) * 2;

    const float* Aptr = A + (size_t)(rowBase + aRow) * lda + aCol;
    const float* Bptr = B + (size_t)bRow * ldb + colBase + bCol;

    const int tr8 = (tid >> 4) * 8;
    const int tc4 = (tid & 15) * 4;

    float acc[8][4];
    #pragma unroll
    for (int m = 0; m < 8; m++)
        #pragma unroll
        for (int n = 0; n < 4; n++) acc[m][n] = 0.0f;

    float4 a4 = *(const float4*)(Aptr);
    float2 b2 = *(const float2*)(Bptr);
    As[0][aCol + 0][aRow] = a4.x;
    As[0][aCol + 1][aRow] = a4.y;
    As[0][aCol + 2][aRow] = a4.z;
    As[0][aCol + 3][aRow] = a4.w;
    *(float2*)&Bs[0][bRow][bCol] = b2;
    __syncthreads();

    int buf = 0;
    for (int k0 = 0; k0 < K; k0 += GBK) {
        const bool has_next = (k0 + GBK) < K;
        if (has_next) {
            a4 = *(const float4*)(Aptr + k0 + GBK);
            b2 = *(const float2*)(Bptr + (size_t)(k0 + GBK) * ldb);
        }
        #pragma unroll
        for (int kk = 0; kk < GBK; kk++) {
            float4 ra0 = *(const float4*)&As[buf][kk][tr8];
            float4 ra1 = *(const float4*)&As[buf][kk][tr8 + 4];
            float4 rb  = *(const float4*)&Bs[buf][kk][tc4];
            float ra[8] = {ra0.x, ra0.y, ra0.z, ra0.w, ra1.x, ra1.y, ra1.z, ra1.w};
            float rbv[4] = {rb.x, rb.y, rb.z, rb.w};
            #pragma unroll
            for (int m = 0; m < 8; m++)
                #pragma unroll
                for (int n = 0; n < 4; n++)
                    acc[m][n] = fmaf(ra[m], rbv[n], acc[m][n]);
        }
        if (has_next) {
            const int nb = buf ^ 1;
            As[nb][aCol + 0][aRow] = a4.x;
            As[nb][aCol + 1][aRow] = a4.y;
            As[nb][aCol + 2][aRow] = a4.z;
            As[nb][aCol + 3][aRow] = a4.w;
            *(float2*)&Bs[nb][bRow][bCol] = b2;
            __syncthreads();
            buf = nb;
        }
    }

    #pragma unroll
    for (int m = 0; m < 8; m++) {
        const int row = rowBase + tr8 + m;
        const int col = colBase + tc4;
        float vx = acc[m][0] + bias[col + 0];
        float vy = acc[m][1] + bias[col + 1];
        float vz = acc[m][2] + bias[col + 2];
        float vw = acc[m][3] + bias[col + 3];
        uint32_t h0 = pack_hi(vx, vy), h1 = pack_hi(vz, vw);
        uint32_t l0 = pack_lo(vx, vy, h0), l1 = pack_lo(vz, vw, h1);
        uint2 H; H.x = h0; H.y = h1;
        uint2 L; L.x = l0; L.y = l1;
        *(uint2*)&Ohi[(size_t)row * (2 * HID) + col] = H;
        *(uint2*)&Olo[(size_t)row * (2 * HID) + col] = L;
    }
}

// =====================================================================
// K2 via HMMA, cp.async double-buffered staging (96KB dynamic smem).
// =====================================================================
__global__ __launch_bounds__(256) void k2_hmma(
    const __nv_bfloat16* __restrict__ Ahi, const __nv_bfloat16* __restrict__ Alo,
    const __nv_bfloat16* __restrict__ Bhi, const __nv_bfloat16* __restrict__ Blo,
    const float* __restrict__ bpc,
    float* __restrict__ hc, float* __restrict__ tcat)
{
    extern __shared__ char smem[];
    const uint32_t sb = smem_u32(smem);
    const int tid = threadIdx.x;
    const int wid = tid >> 5;
    const int lane = tid & 31;
    const int bx = blockIdx.x;
    const int by = blockIdx.y;
    const int z = blockIdx.z;
    const int koff = z * HID;

    const int m0 = (wid >> 1) * 32;
    const int n0 = (wid & 1) * 32;

    float acc[2][4][4];
    #pragma unroll
    for (int mf = 0; mf < 2; mf++)
        #pragma unroll
        for (int nf = 0; nf < 4; nf++)
            #pragma unroll
            for (int e = 0; e < 4; e++) acc[mf][nf][e] = 0.0f;

    const int aRowOff = (m0 + (lane & 15)) * 128 + ((lane & 16) ? 16 : 0);
    const int bRowOff = (n0 + (lane & 7) + ((lane & 16) ? 8 : 0)) * 128 + ((lane & 8) ? 16 : 0);

    auto STAGE = [&](int ch, int stg) {
        const int k0 = koff + ch * K2_BK;
        const uint32_t base = sb + stg * K2_STAGE;
        #pragma unroll
        for (int it = 0; it < 4; it++) {
            const int g = tid + it * 256;
            const int row = g >> 3, grp = g & 7;
            const size_t src = (size_t)(by * 128 + row) * (2 * HID) + k0 + grp * 8;
            const uint32_t off = SWZ128((uint32_t)(row * 128 + grp * 16));
            cp16(base + S_AHI + off, Ahi + src);
            cp16(base + S_ALO + off, Alo + src);
        }
        #pragma unroll
        for (int it = 0; it < 2; it++) {
            const int g = tid + it * 256;
            const int row = g >> 3, grp = g & 7;
            const size_t src = (size_t)(bx * 64 + row) * (2 * HID) + k0 + grp * 8;
            const uint32_t off = SWZ128((uint32_t)(row * 128 + grp * 16));
            cp16(base + S_BHI + off, Bhi + src);
            cp16(base + S_BLO + off, Blo + src);
        }
        CP_COMMIT();
    };

    STAGE(0, 0);
    int buf = 0;
    for (int ch = 0; ch < K2_NCH; ch++) {
        const bool nxt = (ch + 1) < K2_NCH;
        if (nxt) STAGE(ch + 1, buf ^ 1);
        if (nxt) CP_WAIT1(); else CP_WAIT0();
        __syncthreads();

        const uint32_t base = sb + buf * K2_STAGE;
        #pragma unroll
        for (int kk = 0; kk < K2_BK; kk += 16) {
            uint32_t ahi[2][4], alo[2][4], bh[2][4], bl[2][4];
            #pragma unroll
            for (int mf = 0; mf < 2; mf++) {
                const uint32_t off = SWZ128((uint32_t)(aRowOff + mf * 16 * 128 + kk * 2));
                ldsm_x4(ahi[mf], base + S_AHI + off);
                ldsm_x4(alo[mf], base + S_ALO + off);
            }
            #pragma unroll
            for (int nf2 = 0; nf2 < 2; nf2++) {
                const uint32_t off = SWZ128((uint32_t)(bRowOff + nf2 * 16 * 128 + kk * 2));
                ldsm_x4(bh[nf2], base + S_BHI + off);
                ldsm_x4(bl[nf2], base + S_BLO + off);
            }
            #pragma unroll
            for (int mf = 0; mf < 2; mf++) {
                #pragma unroll
                for (int nf = 0; nf < 4; nf++) {
                    const uint32_t* bhp = &bh[nf >> 1][(nf & 1) * 2];
                    const uint32_t* blp = &bl[nf >> 1][(nf & 1) * 2];
                    mma_bf16(acc[mf][nf], ahi[mf], bhp);
                    mma_bf16(acc[mf][nf], ahi[mf], blp);
                    mma_bf16(acc[mf][nf], alo[mf], bhp);
                }
            }
        }
        __syncthreads();
        buf ^= 1;
    }

    const int gm = by * 128 + m0 + (lane >> 2);
    const int gn = bx * 64 + n0 + (lane & 3) * 2;
    float* Cb = (z == 0 ? hc : tcat);
    #pragma unroll
    for (int mf = 0; mf < 2; mf++) {
        #pragma unroll
        for (int nf = 0; nf < 4; nf++) {
            const int col = gn + nf * 8;
            float b0 = 0.0f, b1 = 0.0f;
            if (z == 0) { b0 = bpc[col]; b1 = bpc[col + 1]; }
            const int r0 = gm + mf * 16;
            float2 v0, v1;
            v0.x = acc[mf][nf][0] + b0;
            v0.y = acc[mf][nf][1] + b1;
            v1.x = acc[mf][nf][2] + b0;
            v1.y = acc[mf][nf][3] + b1;
            *(float2*)&Cb[(size_t)r0 * POOL + col] = v0;
            *(float2*)&Cb[(size_t)(r0 + 8) * POOL + col] = v1;
        }
    }
}

// =====================================================================
// K3 via HMMA, pipelined:
//  - U prefetched into regs at iter top (hidden behind MMA)
//  - W tiles via depth-2 cp.async
//  - h/t gathers (L2-resident) + A pack/store at iter bottom
// 64KB dynamic smem (2 stages x 32KB).
// =====================================================================
__global__ __launch_bounds__(256) void k3_hmma(
    const float* __restrict__ U,
    const float* __restrict__ HC,
    const float* __restrict__ TC,
    const __nv_bfloat16* __restrict__ Whi,
    const __nv_bfloat16* __restrict__ Wlo,
    const int* __restrict__ pair_idx,
    float* __restrict__ part)
{
    extern __shared__ char smem[];
    const uint32_t sb = smem_u32(smem);
    const int tid = threadIdx.x;
    const int wid = tid >> 5;
    const int lane = tid & 31;
    const int rBase = blockIdx.x * R3_M;
    const int sp = blockIdx.y;
    const int kb = sp * R3_KS;

    const int m0 = (wid >> 2) * 32;
    const int n0 = (wid & 3) * 16;

    const int sRow = tid >> 2;
    const int sK = (tid & 3) * 16;
    const int grow = rBase + sRow;
    const int si = pair_idx[2 * grow];
    const int sj = pair_idx[2 * grow + 1];
    const float* hp = HC + (size_t)si * POOL + kb + sK;
    const float* tp = TC + (size_t)sj * POOL + kb + sK;
    const float* up = U  + (size_t)grow * POOL + kb + sK;
    const int sgrp = (tid & 3) * 2;

    float4 ru[4];

    auto ULOAD = [&](int ch) {
        #pragma unroll
        for (int s = 0; s < 4; s++)
            ru[s] = *(const float4*)(up + ch * R3_BK + s * 4);
    };
    auto ASTORE = [&](int ch, int stg) {
        const uint32_t base = sb + stg * R3_STAGE;
        float mv[16];
        #pragma unroll
        for (int s = 0; s < 4; s++) {
            const float4 h = *(const float4*)(hp + ch * R3_BK + s * 4);
            const float4 t = *(const float4*)(tp + ch * R3_BK + s * 4);
            mv[s * 4 + 0] = (h.x + t.x) * ru[s].x;
            mv[s * 4 + 1] = (h.y + t.y) * ru[s].y;
            mv[s * 4 + 2] = (h.z + t.z) * ru[s].z;
            mv[s * 4 + 3] = (h.w + t.w) * ru[s].w;
        }
        #pragma unroll
        for (int g2 = 0; g2 < 2; g2++) {
            uint4 hw, lw;
            uint32_t* hp4 = (uint32_t*)&hw;
            uint32_t* lp4 = (uint32_t*)&lw;
            #pragma unroll
            for (int p = 0; p < 4; p++) {
                const float a = mv[g2 * 8 + p * 2];
                const float b = mv[g2 * 8 + p * 2 + 1];
                hp4[p] = pack_hi(a, b);
                lp4[p] = pack_lo(a, b, hp4[p]);
            }
            const uint32_t dst = SWZ128((uint32_t)(sRow * 128 + (sgrp + g2) * 16));
            *(uint4*)(smem + stg * R3_STAGE + R3_AHI + dst) = hw;
            *(uint4*)(smem + stg * R3_STAGE + R3_ALO + dst) = lw;
        }
        (void)base;
    };
    auto BSTAGE = [&](int ch, int stg) {
        const uint32_t base = sb + stg * R3_STAGE;
        #pragma unroll
        for (int it = 0; it < 2; it++) {
            const int g = tid + it * 256;
            const int row = g >> 3, grp = g & 7;
            const size_t src = (size_t)row * POOL + kb + ch * R3_BK + grp * 8;
            const uint32_t off = SWZ128((uint32_t)(row * 128 + grp * 16));
            cp16(base + R3_BHI + off, Whi + src);
            cp16(base + R3_BLO + off, Wlo + src);
        }
        CP_COMMIT();
    };

    float acc[2][2][4];
    #pragma unroll
    for (int mf = 0; mf < 2; mf++)
        #pragma unroll
        for (int nf = 0; nf < 2; nf++)
            #pragma unroll
            for (int e = 0; e < 4; e++) acc[mf][nf][e] = 0.0f;

    const int aRowOff = (m0 + (lane & 15)) * 128 + ((lane & 16) ? 16 : 0);
    const int bRowOff = (n0 + (lane & 7) + ((lane & 16) ? 8 : 0)) * 128 + ((lane & 8) ? 16 : 0);

    // prologue: A(0) (stalls once), B(0), B(1)
    ULOAD(0);
    ASTORE(0, 0);
    BSTAGE(0, 0);
    BSTAGE(1, 1);

    int buf = 0;
    for (int ch = 0; ch < R3_NCH; ch++) {
        const bool nxt = (ch + 1) < R3_NCH;
        if (nxt) CP_WAIT1(); else CP_WAIT0();
        __syncthreads();

        if (nxt) ULOAD(ch + 1);   // LDG issue; consumed only after MMA

        const uint32_t base = sb + buf * R3_STAGE;
        #pragma unroll
        for (int kk = 0; kk < R3_BK; kk += 16) {
            uint32_t ahi[2][4], alo[2][4], bh[4], bl[4];
            #pragma unroll
            for (int mf = 0; mf < 2; mf++) {
                const uint32_t off = SWZ128((uint32_t)(aRowOff + mf * 16 * 128 + kk * 2));
                ldsm_x4(ahi[mf], base + R3_AHI + off);
                ldsm_x4(alo[mf], base + R3_ALO + off);
            }
            {
                const uint32_t off = SWZ128((uint32_t)(bRowOff + kk * 2));
                ldsm_x4(bh, base + R3_BHI + off);
                ldsm_x4(bl, base + R3_BLO + off);
            }
            #pragma unroll
            for (int mf = 0; mf < 2; mf++) {
                #pragma unroll
                for (int nf = 0; nf < 2; nf++) {
                    const uint32_t* bhp = &bh[nf * 2];
                    const uint32_t* blp = &bl[nf * 2];
                    mma_bf16(acc[mf][nf], ahi[mf], bhp);
                    mma_bf16(acc[mf][nf], ahi[mf], blp);
                    mma_bf16(acc[mf][nf], alo[mf], bhp);
                }
            }
        }
        __syncthreads();

        if (nxt) {
            ASTORE(ch + 1, buf ^ 1);
            if (ch + 2 < R3_NCH) BSTAGE(ch + 2, buf);
        }
        buf ^= 1;
    }

    const int gm = rBase + m0 + (lane >> 2);
    const int gn = n0 + (lane & 3) * 2;
    float* pb = part + (size_t)sp * N_REL * NPAD;
    #pragma unroll
    for (int mf = 0; mf < 2; mf++) {
        #pragma unroll
        for (int nf = 0; nf < 2; nf++) {
            const int col = gn + nf * 8;
            const int r0 = gm + mf * 16;
            float2 v0, v1;
            v0.x = acc[mf][nf][0];
            v0.y = acc[mf][nf][1];
            v1.x = acc[mf][nf][2];
            v1.y = acc[mf][nf][3];
            *(float2*)&pb[(size_t)r0 * NPAD + col] = v0;
            *(float2*)&pb[(size_t)(r0 + 8) * NPAD + col] = v1;
        }
    }
}

// =====================================================================
// combine
// =====================================================================
__global__ __launch_bounds__(256) void combine_rel(
    const float* __restrict__ part,
    const float* __restrict__ br,
    const float* __restrict__ freq,
    const int* __restrict__ pair_idx,
    const int* __restrict__ obj_preds,
    float* __restrict__ out)
{
    const int r = blockIdx.x * 4 + (threadIdx.x >> 6);
    const int c = threadIdx.x & 63;
    if (c >= NUM_REL_CLS) return;

    const int bi = obj_preds[pair_idx[2 * r]] * NUM_OBJ_CLS
                 + obj_preds[pair_idx[2 * r + 1]];
    float s = 0.0f;
    #pragma unroll
    for (int sp = 0; sp < R3_SPLITK; sp++)
        s += part[((size_t)sp * N_REL + r) * NPAD + c];
    out[(size_t)r * NUM_REL_CLS + c] = s + br[c] + freq[(size_t)bi * NUM_REL_CLS + c];
}

// =====================================================================
// Launch
// =====================================================================
extern "C" void kernel_launch(void* const* d_in, const int* in_sizes, int n_in,
                              void* d_out, int out_size)
{
    const float* edge_ctx   = (const float*)d_in[0];
    const float* U          = (const float*)d_in[1];
    const float* W_post_emb = (const float*)d_in[2];
    const float* b_post_emb = (const float*)d_in[3];
    const float* W_post_cat = (const float*)d_in[4];
    const float* b_post_cat = (const float*)d_in[5];
    const float* W_rel      = (const float*)d_in[6];
    const float* b_rel      = (const float*)d_in[7];
    const float* freq       = (const float*)d_in[8];
    const int*   pair_idx   = (const int*)d_in[9];
    const int*   obj_preds  = (const int*)d_in[10];
    float* out = (float*)d_out;

    float *hc, *tc, *part;
    __nv_bfloat16 *ahi, *alo, *bhi, *blo, *whi, *wlo;
    cudaGetSymbolAddress((void**)&hc, g_head_cat);
    cudaGetSymbolAddress((void**)&tc, g_tail_cat);
    cudaGetSymbolAddress((void**)&part, g_part);
    cudaGetSymbolAddress((void**)&ahi, g_A_hi);
    cudaGetSymbolAddress((void**)&alo, g_A_lo);
    cudaGetSymbolAddress((void**)&bhi, g_Bt_hi);
    cudaGetSymbolAddress((void**)&blo, g_Bt_lo);
    cudaGetSymbolAddress((void**)&whi, g_Wt_hi);
    cudaGetSymbolAddress((void**)&wlo, g_Wt_lo);

    static bool attr_done = false;
    if (!attr_done) {
        cudaFuncSetAttribute(k2_hmma, cudaFuncAttributeMaxDynamicSharedMemorySize,
                             2 * K2_STAGE);
        cudaFuncSetAttribute(k3_hmma, cudaFuncAttributeMaxDynamicSharedMemorySize,
                             2 * R3_STAGE);
        attr_done = true;
    }

    // weight preprocessing (independent of K1)
    transpose_split_Wrel<<<dim3(NPAD / 32, POOL / 32), 256>>>(W_rel, whi, wlo);
    transpose_split_B<<<dim3(POOL / 32, (2 * HID) / 32), 256>>>(W_post_cat, bhi, blo);

    // K1: edge_rep GEMM, fused bf16 hi/lo split epilogue
    k1_gemm<<<dim3((2 * HID) / GBN, N_OBJ / GBM), 256>>>(
        edge_ctx, W_post_emb, b_post_emb, ahi, alo);

    // K2: head_cat / tail_cat via HMMA + cp.async pipeline
    k2_hmma<<<dim3(POOL / 64, N_OBJ / 128, 2), 256, 2 * K2_STAGE>>>(
        ahi, alo, bhi, blo, b_post_cat, hc, tc);

    // K3: fused gather+elementwise GEMM via HMMA, pipelined
    k3_hmma<<<dim3(N_REL / R3_M, R3_SPLITK), 256, 2 * R3_STAGE>>>(
        U, hc, tc, whi, wlo, pair_idx, part);

    // K4: combine
    combine_rel<<<N_REL / 4, 256>>>(part, b_rel, freq, pair_idx, obj_preds, out);
}